// round 3
// baseline (speedup 1.0000x reference)
#include <cuda_runtime.h>
#include <cuda_bf16.h>

// Problem constants (fixed by the dataset)
#define BB   16
#define SS   2048
#define DD   240
#define EE   8
#define TT   (BB * SS)        // 32768 tokens

// GEMM tiling
#define TM   64               // tokens per tile
#define TN   80               // outputs per tile (240 = 3 * 80)
#define KC   48               // K chunk (240 = 5 * 48)
#define KSTR (KC + 4)         // smem row stride in floats (52: 16B aligned)

// Packed fp32x2 FMA — sm_103a FFMA2, only reachable via PTX (SASS_QUICKREF).
#define FMA_F32X2(d, a, b, c) \
    asm("fma.rn.f32x2 %0, %1, %2, %3;" : "=l"(d) : "l"(a), "l"(b), "l"(c))

// Scratch (device globals — no allocation allowed in kernel_launch)
__device__ int   g_cnt[EE];
__device__ int   g_tok[EE][TT];
__device__ float g_gw [EE][TT];

// ---------------------------------------------------------------------------
// Kernel 0: zero output + per-expert counters
// ---------------------------------------------------------------------------
__global__ void zero_kernel(float4* __restrict__ out4, int n4) {
    int i = blockIdx.x * blockDim.x + threadIdx.x;
    if (i < n4) out4[i] = make_float4(0.f, 0.f, 0.f, 0.f);
    if (blockIdx.x == 0 && threadIdx.x < EE) g_cnt[threadIdx.x] = 0;
}

// ---------------------------------------------------------------------------
// Kernel 1: gating — one warp per token.
// renormalized top-2 softmax weights == 2-way softmax over the top-2 logits.
// ---------------------------------------------------------------------------
__global__ __launch_bounds__(256)
void gate_kernel(const float* __restrict__ x,
                 const float* __restrict__ gw,
                 const float* __restrict__ gb) {
    int warp = (blockIdx.x * blockDim.x + threadIdx.x) >> 5;
    int lane = threadIdx.x & 31;
    if (warp >= TT) return;

    const float* xp = x + (long)warp * DD;
    float xv[8];
#pragma unroll
    for (int i = 0; i < 8; i++) {
        int d = lane + 32 * i;
        xv[i] = (d < DD) ? xp[d] : 0.f;
    }

    float l[EE];
#pragma unroll
    for (int e = 0; e < EE; e++) {
        const float* wp = gw + e * DD;
        float s = 0.f;
#pragma unroll
        for (int i = 0; i < 8; i++) {
            int d = lane + 32 * i;
            s += xv[i] * ((d < DD) ? wp[d] : 0.f);
        }
#pragma unroll
        for (int o = 16; o > 0; o >>= 1) s += __shfl_xor_sync(0xffffffffu, s, o);
        l[e] = s + gb[e];
    }

    if (lane == 0) {
        int b1 = 0;
#pragma unroll
        for (int e = 1; e < EE; e++) if (l[e] > l[b1]) b1 = e;
        int b2 = (b1 == 0) ? 1 : 0;
#pragma unroll
        for (int e = 0; e < EE; e++) {
            if (e == b1 || e == b2) continue;
            if (l[e] > l[b2]) b2 = e;
        }
        float m  = fmaxf(l[b1], l[b2]);
        float e1 = __expf(l[b1] - m);
        float e2 = __expf(l[b2] - m);
        float inv = 1.f / (e1 + e2);
        int p1 = atomicAdd(&g_cnt[b1], 1);
        g_tok[b1][p1] = warp;  g_gw[b1][p1] = e1 * inv;
        int p2 = atomicAdd(&g_cnt[b2], 1);
        g_tok[b2][p2] = warp;  g_gw[b2][p2] = e2 * inv;
    }
}

// ---------------------------------------------------------------------------
// Kernel 2: grouped expert GEMM with packed f32x2 FMA.
// grid = (T/TM, 240/TN, E). Block: 256 threads, 4x5 register tile,
// accumulators hold packed (even-k, odd-k) partial sums.
// ---------------------------------------------------------------------------
__global__ __launch_bounds__(256)
void moe_gemm_kernel(const float* __restrict__ x,
                     const float* __restrict__ ew,
                     const float* __restrict__ eb,
                     float* __restrict__ out) {
    int e   = blockIdx.z;
    int cnt = g_cnt[e];
    int m0  = blockIdx.x * TM;
    if (m0 >= cnt) return;
    int n0  = blockIdx.y * TN;

    __shared__ float Xs[TM][KSTR];
    __shared__ float Ws[TN][KSTR];
    __shared__ int   ts[TM];
    __shared__ float ws[TM];

    int tid = threadIdx.x;
    if (tid < TM) {
        int gr = m0 + tid;
        if (gr < cnt) { ts[tid] = g_tok[e][gr]; ws[tid] = g_gw[e][gr]; }
        else          { ts[tid] = -1;           ws[tid] = 0.f; }
    }
    __syncthreads();

    int tm = tid & 15;   // m group: m = tm + 16*i
    int tn = tid >> 4;   // n group: n = tn + 16*j

    // packed accumulators: low 32 bits = even-k partial sum, high = odd-k
    unsigned long long acc2[4][5] = {};   // bit pattern 0 == (0.f, 0.f)

    const float* wbase = ew + (long)e * DD * DD;

    for (int k0 = 0; k0 < DD; k0 += KC) {
        // load X tile: TM x KC as float4
        for (int idx = tid; idx < TM * (KC / 4); idx += 256) {
            int r = idx / (KC / 4);
            int c = idx % (KC / 4);
            float4 v = make_float4(0.f, 0.f, 0.f, 0.f);
            int t = ts[r];
            if (t >= 0) v = *(const float4*)(x + (long)t * DD + k0 + c * 4);
            *(float4*)&Xs[r][c * 4] = v;
        }
        // load W tile: TN x KC as float4
        for (int idx = tid; idx < TN * (KC / 4); idx += 256) {
            int r = idx / (KC / 4);
            int c = idx % (KC / 4);
            float4 v = *(const float4*)(wbase + (long)(n0 + r) * DD + k0 + c * 4);
            *(float4*)&Ws[r][c * 4] = v;
        }
        __syncthreads();

#pragma unroll
        for (int kk = 0; kk < KC; kk += 4) {
            ulonglong2 xm[4];   // .x = floats (kk,kk+1), .y = floats (kk+2,kk+3)
            ulonglong2 wn[5];
#pragma unroll
            for (int i = 0; i < 4; i++)
                xm[i] = *(const ulonglong2*)&Xs[tm + 16 * i][kk];
#pragma unroll
            for (int j = 0; j < 5; j++)
                wn[j] = *(const ulonglong2*)&Ws[tn + 16 * j][kk];
#pragma unroll
            for (int i = 0; i < 4; i++) {
#pragma unroll
                for (int j = 0; j < 5; j++) {
                    FMA_F32X2(acc2[i][j], xm[i].x, wn[j].x, acc2[i][j]);
                    FMA_F32X2(acc2[i][j], xm[i].y, wn[j].y, acc2[i][j]);
                }
            }
        }
        __syncthreads();
    }

    // epilogue: out[t, n0+n] += w * (acc + b_e[n0+n])
#pragma unroll
    for (int i = 0; i < 4; i++) {
        int r = tm + 16 * i;
        int t = ts[r];
        if (t < 0) continue;
        float w = ws[r];
        float* op = out + (long)t * DD + n0;
        const float* bp = eb + e * DD + n0;
#pragma unroll
        for (int j = 0; j < 5; j++) {
            int n = tn + 16 * j;
            float lo = __uint_as_float((unsigned)(acc2[i][j] & 0xffffffffull));
            float hi = __uint_as_float((unsigned)(acc2[i][j] >> 32));
            atomicAdd(&op[n], w * (lo + hi + bp[n]));
        }
    }
}

// ---------------------------------------------------------------------------
extern "C" void kernel_launch(void* const* d_in, const int* in_sizes, int n_in,
                              void* d_out, int out_size) {
    const float* x  = (const float*)d_in[0];   // [B,S,D]
    const float* gw = (const float*)d_in[1];   // [E,D]
    const float* gb = (const float*)d_in[2];   // [E]
    const float* ew = (const float*)d_in[3];   // [E,D,D]
    const float* eb = (const float*)d_in[4];   // [E,D]
    float* out = (float*)d_out;                // [B,S,D] fp32

    int n4 = out_size / 4;
    zero_kernel<<<(n4 + 255) / 256, 256>>>((float4*)out, n4);

    gate_kernel<<<(TT * 32) / 256, 256>>>(x, gw, gb);

    dim3 grid(TT / TM, DD / TN, EE);           // (512, 3, 8)
    moe_gemm_kernel<<<grid, 256>>>(x, ew, eb, out);
}

// round 5
// speedup vs baseline: 1.5438x; 1.5438x over previous
#include <cuda_runtime.h>
#include <cuda_bf16.h>
#include <cstdint>

// Problem constants (fixed by the dataset)
#define BB   16
#define SS   2048
#define DD   240
#define EE   8
#define TT   (BB * SS)        // 32768 tokens

#define KCH     16            // k per chunk (one mma K)
#define NCHUNK  (DD / KCH)    // 15
#define BM      128           // tokens per CTA tile
#define BN      240           // full output row per CTA

// ---------------------------------------------------------------------------
// Device-global scratch (no runtime allocation allowed)
// ---------------------------------------------------------------------------
__device__ int   g_cnt[EE];
__device__ int   g_tok[EE][TT];
__device__ float g_gw [EE][TT];
__device__ __align__(16) unsigned short g_xh[TT * DD];       // bf16 hi of x
__device__ __align__(16) unsigned short g_xl[TT * DD];       // bf16 lo of x
__device__ __align__(16) unsigned short g_wh[EE * DD * DD];  // bf16 hi of W
__device__ __align__(16) unsigned short g_wl[EE * DD * DD];  // bf16 lo of W

// ---------------------------------------------------------------------------
// PTX helpers
// ---------------------------------------------------------------------------
__device__ __forceinline__ void cp16(uint32_t dst, const void* src, int sz) {
    asm volatile("cp.async.ca.shared.global [%0], [%1], 16, %2;"
                 :: "r"(dst), "l"(src), "r"(sz));
}
#define CP_COMMIT() asm volatile("cp.async.commit_group;")
#define CP_WAIT(n)  asm volatile("cp.async.wait_group %0;" :: "n"(n))

__device__ __forceinline__ void ldm_x4(uint32_t (&r)[4], uint32_t addr) {
    asm volatile("ldmatrix.sync.aligned.m8n8.x4.shared.b16 {%0,%1,%2,%3}, [%4];"
                 : "=r"(r[0]), "=r"(r[1]), "=r"(r[2]), "=r"(r[3]) : "r"(addr));
}
__device__ __forceinline__ void ldm_x2(uint32_t& r0, uint32_t& r1, uint32_t addr) {
    asm volatile("ldmatrix.sync.aligned.m8n8.x2.shared.b16 {%0,%1}, [%2];"
                 : "=r"(r0), "=r"(r1) : "r"(addr));
}
__device__ __forceinline__ void mma_bf16(float (&d)[4], const uint32_t (&a)[4],
                                         uint32_t b0, uint32_t b1) {
    asm volatile("mma.sync.aligned.m16n8k16.row.col.f32.bf16.bf16.f32 "
                 "{%0,%1,%2,%3}, {%4,%5,%6,%7}, {%8,%9}, {%0,%1,%2,%3};"
                 : "+f"(d[0]), "+f"(d[1]), "+f"(d[2]), "+f"(d[3])
                 : "r"(a[0]), "r"(a[1]), "r"(a[2]), "r"(a[3]), "r"(b0), "r"(b1));
}

// ---------------------------------------------------------------------------
// Kernel 0: zero output + per-expert counters
// ---------------------------------------------------------------------------
__global__ void zero_kernel(float4* __restrict__ out4, int n4) {
    int i = blockIdx.x * blockDim.x + threadIdx.x;
    if (i < n4) out4[i] = make_float4(0.f, 0.f, 0.f, 0.f);
    if (blockIdx.x == 0 && threadIdx.x < EE) g_cnt[threadIdx.x] = 0;
}

// ---------------------------------------------------------------------------
// Kernel 1a/1b: fp32 -> bf16 (hi, lo) split conversion, 8 elems/thread
// ---------------------------------------------------------------------------
__global__ __launch_bounds__(256)
void conv_kernel(const float* __restrict__ src,
                 unsigned short* __restrict__ dh,
                 unsigned short* __restrict__ dl, int n8) {
    int i = blockIdx.x * blockDim.x + threadIdx.x;
    if (i >= n8) return;
    const float4* s4 = (const float4*)(src + (size_t)i * 8);
    float4 v0 = s4[0], v1 = s4[1];
    float v[8] = {v0.x, v0.y, v0.z, v0.w, v1.x, v1.y, v1.z, v1.w};
    unsigned short h[8], l[8];
#pragma unroll
    for (int j = 0; j < 8; j++) {
        __nv_bfloat16 hi = __float2bfloat16(v[j]);
        __nv_bfloat16 lo = __float2bfloat16(v[j] - __bfloat162float(hi));
        h[j] = *(unsigned short*)&hi;
        l[j] = *(unsigned short*)&lo;
    }
    *(uint4*)(dh + (size_t)i * 8) = *(uint4*)h;
    *(uint4*)(dl + (size_t)i * 8) = *(uint4*)l;
}

// ---------------------------------------------------------------------------
// Kernel 2: gating — one warp per token (unchanged, proven).
// ---------------------------------------------------------------------------
__global__ __launch_bounds__(256)
void gate_kernel(const float* __restrict__ x,
                 const float* __restrict__ gw,
                 const float* __restrict__ gb) {
    int warp = (blockIdx.x * blockDim.x + threadIdx.x) >> 5;
    int lane = threadIdx.x & 31;
    if (warp >= TT) return;

    const float* xp = x + (long)warp * DD;
    float xv[8];
#pragma unroll
    for (int i = 0; i < 8; i++) {
        int d = lane + 32 * i;
        xv[i] = (d < DD) ? xp[d] : 0.f;
    }
    float l[EE];
#pragma unroll
    for (int e = 0; e < EE; e++) {
        const float* wp = gw + e * DD;
        float s = 0.f;
#pragma unroll
        for (int i = 0; i < 8; i++) {
            int d = lane + 32 * i;
            s += xv[i] * ((d < DD) ? wp[d] : 0.f);
        }
#pragma unroll
        for (int o = 16; o > 0; o >>= 1) s += __shfl_xor_sync(0xffffffffu, s, o);
        l[e] = s + gb[e];
    }
    if (lane == 0) {
        int b1 = 0;
#pragma unroll
        for (int e = 1; e < EE; e++) if (l[e] > l[b1]) b1 = e;
        int b2 = (b1 == 0) ? 1 : 0;
#pragma unroll
        for (int e = 0; e < EE; e++) {
            if (e == b1 || e == b2) continue;
            if (l[e] > l[b2]) b2 = e;
        }
        float m  = fmaxf(l[b1], l[b2]);
        float e1 = __expf(l[b1] - m);
        float e2 = __expf(l[b2] - m);
        float inv = 1.f / (e1 + e2);
        int p1 = atomicAdd(&g_cnt[b1], 1);
        g_tok[b1][p1] = warp;  g_gw[b1][p1] = e1 * inv;
        int p2 = atomicAdd(&g_cnt[b2], 1);
        g_tok[b2][p2] = warp;  g_gw[b2][p2] = e2 * inv;
    }
}

// ---------------------------------------------------------------------------
// Kernel 3: grouped expert GEMM on tensor cores (bf16 split, 3 terms).
// grid = (TT/BM, EE), 256 threads = 8 warps (4 m-warps x 2 n-warps).
// Warp tile: 32 rows x 120 cols = 2 m-tiles x 15 n-tiles of m16n8k16.
// cp.async double-buffered k-chunk pipeline (15 chunks of k=16).
// ---------------------------------------------------------------------------
__global__ __launch_bounds__(256, 1)
void moe_mma_kernel(const float* __restrict__ eb,
                    float* __restrict__ out) {
    const int e   = blockIdx.y;
    const int cnt = g_cnt[e];
    const int m0  = blockIdx.x * BM;
    if (m0 >= cnt) return;

    __shared__ __align__(16) unsigned short Ah[2][BM * KCH];
    __shared__ __align__(16) unsigned short Al[2][BM * KCH];
    __shared__ __align__(16) unsigned short Bh[2][BN * KCH];
    __shared__ __align__(16) unsigned short Bl[2][BN * KCH];
    __shared__ int   ts[BM];
    __shared__ float ws[BM];

    const int tid  = threadIdx.x;
    const int lane = tid & 31;
    const int wid  = tid >> 5;
    const int wm   = wid >> 1;           // 0..3 -> m offset
    const int wn   = wid & 1;            // 0..1 -> n offset
    const int m0w  = wm * 32;

    if (tid < BM) {
        int gr = m0 + tid;
        if (gr < cnt) { ts[tid] = g_tok[e][gr]; ws[tid] = g_gw[e][gr]; }
        else          { ts[tid] = -1;           ws[tid] = 0.f; }
    }
    __syncthreads();

    // --- cp.async issue for chunk c into buffer buf ---
    auto issue = [&](int c, int buf) {
        // A tiles: 128 rows x 32B  = 256 16B segs each (hi, lo)
        {
            int s = tid;                       // exactly one seg per thread
            int row = s >> 1, h = s & 1;
            int t = ts[row];
            long so = (long)(t < 0 ? 0 : t) * DD + c * KCH + h * 8;
            int  sz = (t >= 0) ? 16 : 0;
            uint32_t dof = (uint32_t)((row * KCH + h * 8) * 2);
            cp16((uint32_t)__cvta_generic_to_shared(Ah[buf]) + dof, g_xh + so, sz);
            cp16((uint32_t)__cvta_generic_to_shared(Al[buf]) + dof, g_xl + so, sz);
        }
        // B tiles: 240 rows x 32B = 480 16B segs each (hi, lo)
        for (int s = tid; s < BN * 2; s += 256) {
            int row = s >> 1, h = s & 1;
            long so = ((long)e * DD + row) * DD + c * KCH + h * 8;
            uint32_t dof = (uint32_t)((row * KCH + h * 8) * 2);
            cp16((uint32_t)__cvta_generic_to_shared(Bh[buf]) + dof, g_wh + so, 16);
            cp16((uint32_t)__cvta_generic_to_shared(Bl[buf]) + dof, g_wl + so, 16);
        }
        CP_COMMIT();
    };

    // ldmatrix lane offsets (bytes), fixed across chunks
    const uint32_t a_off0 = (uint32_t)(((m0w + (lane & 15)) * KCH + ((lane >> 4) << 3)) * 2);
    const int      l16    = lane & 15;
    const uint32_t b_off  = (uint32_t)(((wn * 120 + (l16 & 7)) * KCH + ((l16 >> 3) << 3)) * 2);

    float acc[2][15][4] = {};

    issue(0, 0);
    for (int c = 0; c < NCHUNK; c++) {
        const int buf = c & 1;
        if (c + 1 < NCHUNK) { issue(c + 1, buf ^ 1); CP_WAIT(1); }
        else                { CP_WAIT(0); }
        __syncthreads();

        const uint32_t ah_base = (uint32_t)__cvta_generic_to_shared(Ah[buf]);
        const uint32_t al_base = (uint32_t)__cvta_generic_to_shared(Al[buf]);
        const uint32_t bh_base = (uint32_t)__cvta_generic_to_shared(Bh[buf]);
        const uint32_t bl_base = (uint32_t)__cvta_generic_to_shared(Bl[buf]);

        uint32_t ah[2][4], al[2][4];
#pragma unroll
        for (int mt = 0; mt < 2; mt++) {
            uint32_t ao = a_off0 + (uint32_t)(mt * 16 * KCH * 2);
            ldm_x4(ah[mt], ah_base + ao);
            ldm_x4(al[mt], al_base + ao);
        }
#pragma unroll
        for (int jt = 0; jt < 15; jt++) {
            uint32_t bo = b_off + (uint32_t)(jt * 8 * KCH * 2);
            uint32_t bh0, bh1, bl0, bl1;
            ldm_x2(bh0, bh1, bh_base + bo);
            ldm_x2(bl0, bl1, bl_base + bo);
#pragma unroll
            for (int mt = 0; mt < 2; mt++) {
                mma_bf16(acc[mt][jt], ah[mt], bh0, bh1);   // hi * hi
                mma_bf16(acc[mt][jt], ah[mt], bl0, bl1);   // hi * lo
                mma_bf16(acc[mt][jt], al[mt], bh0, bh1);   // lo * hi
            }
        }
        __syncthreads();
    }

    // --- epilogue: out[t, n] += w_t * (acc + bias) via fp32 atomics ---
    const float* bp = eb + e * DD;
#pragma unroll
    for (int mt = 0; mt < 2; mt++) {
        int r1 = m0w + mt * 16 + (lane >> 2);
        int r2 = r1 + 8;
        int t1 = ts[r1], t2 = ts[r2];
        float w1 = ws[r1], w2 = ws[r2];
        float* o1 = out + (long)t1 * DD;
        float* o2 = out + (long)t2 * DD;
#pragma unroll
        for (int jt = 0; jt < 15; jt++) {
            int cc = wn * 120 + jt * 8 + 2 * (lane & 3);
            float b0v = bp[cc], b1v = bp[cc + 1];
            if (t1 >= 0) {
                atomicAdd(&o1[cc],     w1 * (acc[mt][jt][0] + b0v));
                atomicAdd(&o1[cc + 1], w1 * (acc[mt][jt][1] + b1v));
            }
            if (t2 >= 0) {
                atomicAdd(&o2[cc],     w2 * (acc[mt][jt][2] + b0v));
                atomicAdd(&o2[cc + 1], w2 * (acc[mt][jt][3] + b1v));
            }
        }
    }
}

// ---------------------------------------------------------------------------
extern "C" void kernel_launch(void* const* d_in, const int* in_sizes, int n_in,
                              void* d_out, int out_size) {
    const float* x  = (const float*)d_in[0];   // [B,S,D]
    const float* gw = (const float*)d_in[1];   // [E,D]
    const float* gb = (const float*)d_in[2];   // [E]
    const float* ew = (const float*)d_in[3];   // [E,D,D]
    const float* eb = (const float*)d_in[4];   // [E,D]
    float* out = (float*)d_out;                // [B,S,D] fp32

    int n4 = out_size / 4;
    zero_kernel<<<(n4 + 255) / 256, 256>>>((float4*)out, n4);

    unsigned short *xh, *xl, *wh, *wl;
    cudaGetSymbolAddress((void**)&xh, g_xh);
    cudaGetSymbolAddress((void**)&xl, g_xl);
    cudaGetSymbolAddress((void**)&wh, g_wh);
    cudaGetSymbolAddress((void**)&wl, g_wl);

    int nx8 = TT * DD / 8;                     // 983040
    conv_kernel<<<(nx8 + 255) / 256, 256>>>(x, xh, xl, nx8);
    int nw8 = EE * DD * DD / 8;                // 57600
    conv_kernel<<<(nw8 + 255) / 256, 256>>>(ew, wh, wl, nw8);

    gate_kernel<<<(TT * 32) / 256, 256>>>(x, gw, gb);

    dim3 ggrid(TT / BM, EE);                   // (256, 8)
    moe_mma_kernel<<<ggrid, 256>>>(eb, out);
}

// round 7
// speedup vs baseline: 1.9624x; 1.2712x over previous
#include <cuda_runtime.h>
#include <cuda_bf16.h>
#include <cstdint>

// Problem constants (fixed by the dataset)
#define BB   16
#define SS   2048
#define DD   240
#define EE   8
#define TT   (BB * SS)        // 32768 tokens

#define KCH     16            // k per chunk (one mma K)
#define NCHUNK  (DD / KCH)    // 15
#define BM      128           // tokens per CTA tile
#define BN      120           // output cols per CTA (grid.y = 2)

// ---------------------------------------------------------------------------
// Device-global scratch (no runtime allocation allowed)
// ---------------------------------------------------------------------------
__device__ int   g_cnt[EE];
__device__ int   g_tok[EE][TT];       // packed: (token << 1) | slot
__device__ float g_gw [EE][TT];
__device__ int   g_e1[TT], g_e2[TT];  // per-token top-2 expert ids
__device__ float g_w1[TT], g_w2[TT];  // per-token renormalized weights
__device__ __align__(16) unsigned short g_xh[TT * DD];       // bf16 hi of x
__device__ __align__(16) unsigned short g_xl[TT * DD];       // bf16 lo of x
__device__ __align__(16) unsigned short g_wh[EE * DD * DD];  // bf16 hi of W
__device__ __align__(16) unsigned short g_wl[EE * DD * DD];  // bf16 lo of W
__device__ __align__(16) float g_part[2][TT * DD];           // per-slot partials

// ---------------------------------------------------------------------------
// PTX helpers
// ---------------------------------------------------------------------------
__device__ __forceinline__ void cp16(uint32_t dst, const void* src, int sz) {
    asm volatile("cp.async.ca.shared.global [%0], [%1], 16, %2;"
                 :: "r"(dst), "l"(src), "r"(sz));
}
#define CP_COMMIT() asm volatile("cp.async.commit_group;")
#define CP_WAIT(n)  asm volatile("cp.async.wait_group %0;" :: "n"(n))

__device__ __forceinline__ void ldm_x4(uint32_t (&r)[4], uint32_t addr) {
    asm volatile("ldmatrix.sync.aligned.m8n8.x4.shared.b16 {%0,%1,%2,%3}, [%4];"
                 : "=r"(r[0]), "=r"(r[1]), "=r"(r[2]), "=r"(r[3]) : "r"(addr));
}
__device__ __forceinline__ void ldm_x2(uint32_t& r0, uint32_t& r1, uint32_t addr) {
    asm volatile("ldmatrix.sync.aligned.m8n8.x2.shared.b16 {%0,%1}, [%2];"
                 : "=r"(r0), "=r"(r1) : "r"(addr));
}
__device__ __forceinline__ void mma_bf16(float (&d)[4], const uint32_t (&a)[4],
                                         uint32_t b0, uint32_t b1) {
    asm volatile("mma.sync.aligned.m16n8k16.row.col.f32.bf16.bf16.f32 "
                 "{%0,%1,%2,%3}, {%4,%5,%6,%7}, {%8,%9}, {%0,%1,%2,%3};"
                 : "+f"(d[0]), "+f"(d[1]), "+f"(d[2]), "+f"(d[3])
                 : "r"(a[0]), "r"(a[1]), "r"(a[2]), "r"(a[3]), "r"(b0), "r"(b1));
}

// ---------------------------------------------------------------------------
// Kernel 1: W fp32 -> bf16 (hi, lo) split, 8 elems/thread
// ---------------------------------------------------------------------------
__global__ __launch_bounds__(256)
void conv_kernel(const float* __restrict__ src,
                 unsigned short* __restrict__ dh,
                 unsigned short* __restrict__ dl, int n8) {
    int i = blockIdx.x * blockDim.x + threadIdx.x;
    if (i >= n8) return;
    const float4* s4 = (const float4*)(src + (size_t)i * 8);
    float4 v0 = s4[0], v1 = s4[1];
    float v[8] = {v0.x, v0.y, v0.z, v0.w, v1.x, v1.y, v1.z, v1.w};
    unsigned short h[8], l[8];
#pragma unroll
    for (int j = 0; j < 8; j++) {
        __nv_bfloat16 hi = __float2bfloat16(v[j]);
        __nv_bfloat16 lo = __float2bfloat16(v[j] - __bfloat162float(hi));
        h[j] = *(unsigned short*)&hi;
        l[j] = *(unsigned short*)&lo;
    }
    *(uint4*)(dh + (size_t)i * 8) = *(uint4*)h;
    *(uint4*)(dl + (size_t)i * 8) = *(uint4*)l;
}

// ---------------------------------------------------------------------------
// Kernel 2: gating — one warp per token. Computes logits, top-2, writes dense
// per-token results (NO contended atomics). Also converts this token's x row
// to bf16 hi/lo (x is already in registers). Block 0 zeroes g_cnt.
// ---------------------------------------------------------------------------
__global__ __launch_bounds__(256)
void gate_kernel(const float* __restrict__ x,
                 const float* __restrict__ gw,
                 const float* __restrict__ gb) {
    if (blockIdx.x == 0 && threadIdx.x < EE) g_cnt[threadIdx.x] = 0;

    int warp = (blockIdx.x * blockDim.x + threadIdx.x) >> 5;
    int lane = threadIdx.x & 31;
    if (warp >= TT) return;

    const float* xp = x + (long)warp * DD;
    float xv[8];
#pragma unroll
    for (int i = 0; i < 8; i++) {
        int d = lane + 32 * i;
        xv[i] = (d < DD) ? xp[d] : 0.f;
    }

    // fold in x -> bf16 hi/lo conversion (coalesced 2B stores)
#pragma unroll
    for (int i = 0; i < 8; i++) {
        int d = lane + 32 * i;
        if (d < DD) {
            __nv_bfloat16 hi = __float2bfloat16(xv[i]);
            __nv_bfloat16 lo = __float2bfloat16(xv[i] - __bfloat162float(hi));
            g_xh[(long)warp * DD + d] = *(unsigned short*)&hi;
            g_xl[(long)warp * DD + d] = *(unsigned short*)&lo;
        }
    }

    float l[EE];
#pragma unroll
    for (int e = 0; e < EE; e++) {
        const float* wp = gw + e * DD;
        float s = 0.f;
#pragma unroll
        for (int i = 0; i < 8; i++) {
            int d = lane + 32 * i;
            s += xv[i] * ((d < DD) ? wp[d] : 0.f);
        }
#pragma unroll
        for (int o = 16; o > 0; o >>= 1) s += __shfl_xor_sync(0xffffffffu, s, o);
        l[e] = s + gb[e];
    }

    if (lane == 0) {
        int b1 = 0;
#pragma unroll
        for (int e = 1; e < EE; e++) if (l[e] > l[b1]) b1 = e;
        int b2 = (b1 == 0) ? 1 : 0;
#pragma unroll
        for (int e = 0; e < EE; e++) {
            if (e == b1 || e == b2) continue;
            if (l[e] > l[b2]) b2 = e;
        }
        float m  = fmaxf(l[b1], l[b2]);
        float e1 = __expf(l[b1] - m);
        float e2 = __expf(l[b2] - m);
        float inv = 1.f / (e1 + e2);
        g_e1[warp] = b1;  g_w1[warp] = e1 * inv;
        g_e2[warp] = b2;  g_w2[warp] = e2 * inv;
    }
}

// ---------------------------------------------------------------------------
// Kernel 3: scatter — thread per token, warp-aggregated atomics (32x fewer).
// Packs (token << 1) | slot into the expert lists.
// ---------------------------------------------------------------------------
__global__ __launch_bounds__(256)
void scatter_kernel() {
    int t = blockIdx.x * blockDim.x + threadIdx.x;
    if (t >= TT) return;
    int lane = threadIdx.x & 31;

#pragma unroll
    for (int slot = 0; slot < 2; slot++) {
        int   e = slot ? g_e2[t] : g_e1[t];
        float w = slot ? g_w2[t] : g_w1[t];
        unsigned mask = __match_any_sync(0xffffffffu, e);
        int leader = __ffs(mask) - 1;
        int rank   = __popc(mask & ((1u << lane) - 1));
        int base = 0;
        if (lane == leader) base = atomicAdd(&g_cnt[e], __popc(mask));
        base = __shfl_sync(mask, base, leader);
        int pos = base + rank;
        g_tok[e][pos] = (t << 1) | slot;
        g_gw [e][pos] = w;
    }
}

// ---------------------------------------------------------------------------
// Kernel 4: grouped expert GEMM on tensor cores (bf16 split, 3 terms).
// grid = (TT/BM, 2, E). 256 threads = 8 warps (4 m-warps x 2 n-warps).
// n-warp 0: 8 n-tiles (cols 0..63 of this 120-col block); n-warp 1: 7 tiles.
// Epilogue: plain stores into g_part[slot] — NO atomics.
// ---------------------------------------------------------------------------
__global__ __launch_bounds__(256, 2)
void moe_mma_kernel(const float* __restrict__ eb) {
    const int e   = blockIdx.z;
    const int cnt = g_cnt[e];
    const int m0  = blockIdx.x * BM;
    if (m0 >= cnt) return;
    const int nb  = blockIdx.y * BN;      // 0 or 120

    __shared__ __align__(16) unsigned short Ah[2][BM * KCH];
    __shared__ __align__(16) unsigned short Al[2][BM * KCH];
    __shared__ __align__(16) unsigned short Bh[2][BN * KCH];
    __shared__ __align__(16) unsigned short Bl[2][BN * KCH];
    __shared__ int   ts[BM];
    __shared__ float ws[BM];

    const int tid  = threadIdx.x;
    const int lane = tid & 31;
    const int wid  = tid >> 5;
    const int wm   = wid >> 1;           // 0..3 -> m offset
    const int wn   = wid & 1;            // 0..1 -> n offset
    const int m0w  = wm * 32;
    const int njt  = 8 - wn;             // 8 tiles for wn=0, 7 for wn=1

    if (tid < BM) {
        int gr = m0 + tid;
        if (gr < cnt) { ts[tid] = g_tok[e][gr]; ws[tid] = g_gw[e][gr]; }
        else          { ts[tid] = -1;           ws[tid] = 0.f; }
    }
    __syncthreads();

    // --- cp.async issue for chunk c into buffer buf ---
    auto issue = [&](int c, int buf) {
        // A: 128 rows x 2 segs = 256 segs; one per thread (hi + lo)
        {
            int row = tid >> 1, h = tid & 1;
            int v = ts[row];
            int t = (v < 0) ? 0 : (v >> 1);
            long so = (long)t * DD + c * KCH + h * 8;
            int  sz = (v >= 0) ? 16 : 0;
            uint32_t dof = (uint32_t)((row * KCH + h * 8) * 2);
            cp16((uint32_t)__cvta_generic_to_shared(Ah[buf]) + dof, g_xh + so, sz);
            cp16((uint32_t)__cvta_generic_to_shared(Al[buf]) + dof, g_xl + so, sz);
        }
        // B: 120 rows x 2 segs = 240 segs; threads < 240 (hi + lo)
        if (tid < BN * 2) {
            int row = tid >> 1, h = tid & 1;
            long so = ((long)e * DD + nb + row) * DD + c * KCH + h * 8;
            uint32_t dof = (uint32_t)((row * KCH + h * 8) * 2);
            cp16((uint32_t)__cvta_generic_to_shared(Bh[buf]) + dof, g_wh + so, 16);
            cp16((uint32_t)__cvta_generic_to_shared(Bl[buf]) + dof, g_wl + so, 16);
        }
        CP_COMMIT();
    };

    // ldmatrix lane offsets (bytes), fixed across chunks
    const uint32_t a_off0 = (uint32_t)(((m0w + (lane & 15)) * KCH + ((lane >> 4) << 3)) * 2);
    const int      l16    = lane & 15;
    const uint32_t b_off  = (uint32_t)(((wn * 64 + (l16 & 7)) * KCH + ((l16 >> 3) << 3)) * 2);

    float acc[2][8][4] = {};

    issue(0, 0);
    for (int c = 0; c < NCHUNK; c++) {
        const int buf = c & 1;
        if (c + 1 < NCHUNK) { issue(c + 1, buf ^ 1); CP_WAIT(1); }
        else                { CP_WAIT(0); }
        __syncthreads();

        const uint32_t ah_base = (uint32_t)__cvta_generic_to_shared(Ah[buf]);
        const uint32_t al_base = (uint32_t)__cvta_generic_to_shared(Al[buf]);
        const uint32_t bh_base = (uint32_t)__cvta_generic_to_shared(Bh[buf]);
        const uint32_t bl_base = (uint32_t)__cvta_generic_to_shared(Bl[buf]);

        uint32_t ah[2][4], al[2][4];
#pragma unroll
        for (int mt = 0; mt < 2; mt++) {
            uint32_t ao = a_off0 + (uint32_t)(mt * 16 * KCH * 2);
            ldm_x4(ah[mt], ah_base + ao);
            ldm_x4(al[mt], al_base + ao);
        }
#pragma unroll
        for (int jt = 0; jt < 8; jt++) {
            if (jt >= njt) break;
            uint32_t bo = b_off + (uint32_t)(jt * 8 * KCH * 2);
            uint32_t bh0, bh1, bl0, bl1;
            ldm_x2(bh0, bh1, bh_base + bo);
            ldm_x2(bl0, bl1, bl_base + bo);
#pragma unroll
            for (int mt = 0; mt < 2; mt++) {
                mma_bf16(acc[mt][jt], ah[mt], bh0, bh1);   // hi * hi
                mma_bf16(acc[mt][jt], ah[mt], bl0, bl1);   // hi * lo
                mma_bf16(acc[mt][jt], al[mt], bh0, bh1);   // lo * hi
            }
        }
        __syncthreads();
    }

    // --- epilogue: g_part[slot][t][n] = w_t * (acc + bias); plain stores ---
    const float* bp = eb + e * DD;
#pragma unroll
    for (int mt = 0; mt < 2; mt++) {
        int r1 = m0w + mt * 16 + (lane >> 2);
        int r2 = r1 + 8;
        int v1 = ts[r1], v2 = ts[r2];
        float w1 = ws[r1], w2 = ws[r2];
        float* o1 = (v1 < 0) ? nullptr : &g_part[v1 & 1][(long)(v1 >> 1) * DD];
        float* o2 = (v2 < 0) ? nullptr : &g_part[v2 & 1][(long)(v2 >> 1) * DD];
#pragma unroll
        for (int jt = 0; jt < 8; jt++) {
            if (jt >= njt) break;
            int cc = nb + wn * 64 + jt * 8 + 2 * (lane & 3);
            float b0v = bp[cc], b1v = bp[cc + 1];
            if (o1) {
                o1[cc]     = w1 * (acc[mt][jt][0] + b0v);
                o1[cc + 1] = w1 * (acc[mt][jt][1] + b1v);
            }
            if (o2) {
                o2[cc]     = w2 * (acc[mt][jt][2] + b0v);
                o2[cc + 1] = w2 * (acc[mt][jt][3] + b1v);
            }
        }
    }
}

// ---------------------------------------------------------------------------
// Kernel 5: combine — out = part[0] + part[1]  (every element written once
// per slot, so no zeroing needed anywhere).
// ---------------------------------------------------------------------------
__global__ __launch_bounds__(256)
void combine_kernel(float4* __restrict__ out4, int n4) {
    int i = blockIdx.x * blockDim.x + threadIdx.x;
    if (i >= n4) return;
    float4 a = ((const float4*)g_part[0])[i];
    float4 b = ((const float4*)g_part[1])[i];
    out4[i] = make_float4(a.x + b.x, a.y + b.y, a.z + b.z, a.w + b.w);
}

// ---------------------------------------------------------------------------
extern "C" void kernel_launch(void* const* d_in, const int* in_sizes, int n_in,
                              void* d_out, int out_size) {
    const float* x  = (const float*)d_in[0];   // [B,S,D]
    const float* gw = (const float*)d_in[1];   // [E,D]
    const float* gb = (const float*)d_in[2];   // [E]
    const float* ew = (const float*)d_in[3];   // [E,D,D]
    const float* eb = (const float*)d_in[4];   // [E,D]
    float* out = (float*)d_out;                // [B,S,D] fp32

    unsigned short *wh, *wl;
    cudaGetSymbolAddress((void**)&wh, g_wh);
    cudaGetSymbolAddress((void**)&wl, g_wl);

    int nw8 = EE * DD * DD / 8;                // 57600
    conv_kernel<<<(nw8 + 255) / 256, 256>>>(ew, wh, wl, nw8);

    gate_kernel<<<(TT * 32) / 256, 256>>>(x, gw, gb);
    scatter_kernel<<<TT / 256, 256>>>();

    dim3 ggrid(TT / BM, 2, EE);                // (256, 2, 8)
    moe_mma_kernel<<<ggrid, 256>>>(eb);

    int n4 = out_size / 4;                     // 1,966,080
    combine_kernel<<<(n4 + 255) / 256, 256>>>((float4*)out, n4);
}

// round 11
// speedup vs baseline: 2.0841x; 1.0620x over previous
#include <cuda_runtime.h>
#include <cuda_bf16.h>
#include <cstdint>

// Problem constants (fixed by the dataset)
#define BB   16
#define SS   2048
#define DD   240
#define EE   8
#define TT   (BB * SS)        // 32768 tokens

#define KCH     16            // k per chunk (one mma K)
#define NCHUNK  (DD / KCH)    // 15
#define BM      128           // tokens per CTA tile
#define BN      120           // output cols per CTA (grid.y = 2)
#define STRB    48            // smem row stride in BYTES (conflict-free ldmatrix)
#define NSTAGE  4             // cp.async pipeline depth

// ---------------------------------------------------------------------------
// Device-global scratch (no runtime allocation allowed)
// ---------------------------------------------------------------------------
__device__ int   g_cnt[EE];
__device__ int   g_tok[EE][TT];       // packed: (token << 1) | slot
__device__ float g_gw [EE][TT];
__device__ int   g_e1[TT], g_e2[TT];  // per-token top-2 expert ids
__device__ float g_w1[TT], g_w2[TT];  // per-token renormalized weights
__device__ __align__(16) unsigned short g_xh[(size_t)TT * DD];       // bf16 hi of x
__device__ __align__(16) unsigned short g_xl[(size_t)TT * DD];       // bf16 lo of x
__device__ __align__(16) unsigned short g_wh[(size_t)EE * DD * DD];  // bf16 hi of W
__device__ __align__(16) unsigned short g_wl[(size_t)EE * DD * DD];  // bf16 lo of W
__device__ __align__(16) float g_part[2][(size_t)TT * DD];           // per-slot partials

// ---------------------------------------------------------------------------
// PTX helpers
// ---------------------------------------------------------------------------
__device__ __forceinline__ void cp16(uint32_t dst, const void* src, int sz) {
    asm volatile("cp.async.ca.shared.global [%0], [%1], 16, %2;"
                 :: "r"(dst), "l"(src), "r"(sz));
}
#define CP_COMMIT() asm volatile("cp.async.commit_group;")
#define CP_WAIT(n)  asm volatile("cp.async.wait_group %0;" :: "n"(n))

__device__ __forceinline__ void ldm_x4(uint32_t (&r)[4], uint32_t addr) {
    asm volatile("ldmatrix.sync.aligned.m8n8.x4.shared.b16 {%0,%1,%2,%3}, [%4];"
                 : "=r"(r[0]), "=r"(r[1]), "=r"(r[2]), "=r"(r[3]) : "r"(addr));
}
__device__ __forceinline__ void ldm_x2(uint32_t& r0, uint32_t& r1, uint32_t addr) {
    asm volatile("ldmatrix.sync.aligned.m8n8.x2.shared.b16 {%0,%1}, [%2];"
                 : "=r"(r0), "=r"(r1) : "r"(addr));
}
__device__ __forceinline__ void mma_bf16(float (&d)[4], const uint32_t (&a)[4],
                                         uint32_t b0, uint32_t b1) {
    asm volatile("mma.sync.aligned.m16n8k16.row.col.f32.bf16.bf16.f32 "
                 "{%0,%1,%2,%3}, {%4,%5,%6,%7}, {%8,%9}, {%0,%1,%2,%3};"
                 : "+f"(d[0]), "+f"(d[1]), "+f"(d[2]), "+f"(d[3])
                 : "r"(a[0]), "r"(a[1]), "r"(a[2]), "r"(a[3]), "r"(b0), "r"(b1));
}
__device__ __forceinline__ uint32_t smem_u32(const void* p) {
    uint32_t a;
    asm("{ .reg .u64 t; cvta.to.shared.u64 t, %1; cvt.u32.u64 %0, t; }" : "=r"(a) : "l"(p));
    return a;
}

// ---------------------------------------------------------------------------
// Kernel 1: W fp32 -> bf16 (hi, lo) split, 8 elems/thread
// ---------------------------------------------------------------------------
__global__ __launch_bounds__(256)
void conv_kernel(const float* __restrict__ src,
                 unsigned short* __restrict__ dh,
                 unsigned short* __restrict__ dl, int n8) {
    int i = blockIdx.x * blockDim.x + threadIdx.x;
    if (i >= n8) return;
    const float4* s4 = (const float4*)(src + (size_t)i * 8);
    float4 v0 = s4[0], v1 = s4[1];
    float v[8] = {v0.x, v0.y, v0.z, v0.w, v1.x, v1.y, v1.z, v1.w};
    unsigned short h[8], l[8];
#pragma unroll
    for (int j = 0; j < 8; j++) {
        __nv_bfloat16 hi = __float2bfloat16(v[j]);
        __nv_bfloat16 lo = __float2bfloat16(v[j] - __bfloat162float(hi));
        h[j] = *(unsigned short*)&hi;
        l[j] = *(unsigned short*)&lo;
    }
    *(uint4*)(dh + (size_t)i * 8) = *(uint4*)h;
    *(uint4*)(dl + (size_t)i * 8) = *(uint4*)l;
}

// ---------------------------------------------------------------------------
// Kernel 2: gating — one warp per token; dense top-2 outputs, folded x->bf16
// hi/lo conversion. No contended atomics.
// ---------------------------------------------------------------------------
__global__ __launch_bounds__(256)
void gate_kernel(const float* __restrict__ x,
                 const float* __restrict__ gw,
                 const float* __restrict__ gb) {
    if (blockIdx.x == 0 && threadIdx.x < EE) g_cnt[threadIdx.x] = 0;

    int warp = (blockIdx.x * blockDim.x + threadIdx.x) >> 5;
    int lane = threadIdx.x & 31;
    if (warp >= TT) return;

    const float* xp = x + (long)warp * DD;
    float xv[8];
#pragma unroll
    for (int i = 0; i < 8; i++) {
        int d = lane + 32 * i;
        xv[i] = (d < DD) ? xp[d] : 0.f;
    }

#pragma unroll
    for (int i = 0; i < 8; i++) {
        int d = lane + 32 * i;
        if (d < DD) {
            __nv_bfloat16 hi = __float2bfloat16(xv[i]);
            __nv_bfloat16 lo = __float2bfloat16(xv[i] - __bfloat162float(hi));
            g_xh[(size_t)warp * DD + d] = *(unsigned short*)&hi;
            g_xl[(size_t)warp * DD + d] = *(unsigned short*)&lo;
        }
    }

    float l[EE];
#pragma unroll
    for (int e = 0; e < EE; e++) {
        const float* wp = gw + e * DD;
        float s = 0.f;
#pragma unroll
        for (int i = 0; i < 8; i++) {
            int d = lane + 32 * i;
            s += xv[i] * ((d < DD) ? wp[d] : 0.f);
        }
#pragma unroll
        for (int o = 16; o > 0; o >>= 1) s += __shfl_xor_sync(0xffffffffu, s, o);
        l[e] = s + gb[e];
    }

    if (lane == 0) {
        int b1 = 0;
#pragma unroll
        for (int e = 1; e < EE; e++) if (l[e] > l[b1]) b1 = e;
        int b2 = (b1 == 0) ? 1 : 0;
#pragma unroll
        for (int e = 0; e < EE; e++) {
            if (e == b1 || e == b2) continue;
            if (l[e] > l[b2]) b2 = e;
        }
        float m  = fmaxf(l[b1], l[b2]);
        float e1 = __expf(l[b1] - m);
        float e2 = __expf(l[b2] - m);
        float inv = 1.f / (e1 + e2);
        g_e1[warp] = b1;  g_w1[warp] = e1 * inv;
        g_e2[warp] = b2;  g_w2[warp] = e2 * inv;
    }
}

// ---------------------------------------------------------------------------
// Kernel 3: scatter — warp-aggregated atomics; packs (token<<1)|slot.
// ---------------------------------------------------------------------------
__global__ __launch_bounds__(256)
void scatter_kernel() {
    int t = blockIdx.x * blockDim.x + threadIdx.x;
    if (t >= TT) return;
    int lane = threadIdx.x & 31;
#pragma unroll
    for (int slot = 0; slot < 2; slot++) {
        int   e = slot ? g_e2[t] : g_e1[t];
        float w = slot ? g_w2[t] : g_w1[t];
        unsigned mask = __match_any_sync(0xffffffffu, e);
        int leader = __ffs(mask) - 1;
        int rank   = __popc(mask & ((1u << lane) - 1));
        int base = 0;
        if (lane == leader) base = atomicAdd(&g_cnt[e], __popc(mask));
        base = __shfl_sync(mask, base, leader);
        int pos = base + rank;
        g_tok[e][pos] = (t << 1) | slot;
        g_gw [e][pos] = w;
    }
}

// ---------------------------------------------------------------------------
// Kernel 4: grouped expert GEMM on warp tensor cores (bf16 split, 3 terms).
// grid = (TT/BM, 2, E). 256 threads = 8 warps (4 m-warps x 2 n-warps).
// 48B smem row stride -> conflict-free ldmatrix; 4-stage cp.async pipeline.
// Epilogue: plain stores into g_part[slot] — NO atomics.
// ---------------------------------------------------------------------------
#define HDR     1024
#define A_SZ    (BM * STRB)            // 6144 B per (hi|lo) A stage part
#define B_SZ    (BN * STRB)            // 5760 B per (hi|lo) B stage part
#define STG_SZ  (2 * A_SZ + 2 * B_SZ)  // 23808 B per stage
#define OFF_AH  0
#define OFF_AL  A_SZ
#define OFF_BH  (2 * A_SZ)
#define OFF_BL  (2 * A_SZ + B_SZ)
#define SMEM_TOT (HDR + NSTAGE * STG_SZ)   // 96256 B -> 2 CTAs/SM

__global__ __launch_bounds__(256, 2)
void moe_mma_kernel(const float* __restrict__ eb) {
    const int e   = blockIdx.z;
    const int cnt = g_cnt[e];
    const int m0  = blockIdx.x * BM;
    if (m0 >= cnt) return;
    const int nb  = blockIdx.y * BN;      // 0 or 120

    extern __shared__ __align__(16) char smem[];
    int*   tsp = (int*)  smem;
    float* wsp = (float*)(smem + 512);
    const uint32_t sb = smem_u32(smem);

    const int tid  = threadIdx.x;
    const int lane = tid & 31;
    const int wid  = tid >> 5;
    const int wm   = wid >> 1;           // 0..3 -> m offset
    const int wn   = wid & 1;            // 0..1 -> n offset
    const int m0w  = wm * 32;

    if (tid < BM) {
        int gr = m0 + tid;
        if (gr < cnt) { tsp[tid] = g_tok[e][gr]; wsp[tid] = g_gw[e][gr]; }
        else          { tsp[tid] = -1;           wsp[tid] = 0.f; }
    }
    __syncthreads();

    // --- cp.async issue for chunk c into stage stg ---
    auto issue = [&](int c, int stg) {
        uint32_t base = sb + HDR + stg * STG_SZ;
        // A: 128 rows x 2 segs of 16B = 256 segs; one per thread (hi + lo)
        {
            int row = tid >> 1, h = tid & 1;
            int v = tsp[row];
            size_t so = (size_t)((v < 0) ? 0 : (v >> 1)) * DD + c * KCH + h * 8;
            int  sz = (v >= 0) ? 16 : 0;
            uint32_t d = (uint32_t)(row * STRB + h * 16);
            cp16(base + OFF_AH + d, g_xh + so, sz);
            cp16(base + OFF_AL + d, g_xl + so, sz);
        }
        // B: 120 rows x 2 segs = 240 segs; threads < 240 (hi + lo)
        if (tid < BN * 2) {
            int row = tid >> 1, h = tid & 1;
            size_t so = ((size_t)e * DD + nb + row) * DD + c * KCH + h * 8;
            uint32_t d = (uint32_t)(row * STRB + h * 16);
            cp16(base + OFF_BH + d, g_wh + so, 16);
            cp16(base + OFF_BL + d, g_wl + so, 16);
        }
        CP_COMMIT();
    };

    // ldmatrix lane byte offsets (48B row stride), fixed across chunks
    const uint32_t a_off0 = (uint32_t)((m0w + (lane & 15)) * STRB + ((lane >> 4) << 4));
    const int      l16    = lane & 15;
    const uint32_t b_off  = (uint32_t)((wn * 64 + (l16 & 7)) * STRB + ((l16 >> 3) << 4));

    float acc[2][8][4] = {};

    issue(0, 0);
    issue(1, 1);
    issue(2, 2);

    for (int c = 0; c < NCHUNK; c++) {
        const int stg = c & (NSTAGE - 1);
        if (c < NCHUNK - 2)      CP_WAIT(2);
        else if (c == NCHUNK - 2) CP_WAIT(1);
        else                      CP_WAIT(0);
        __syncthreads();

        if (c + 3 < NCHUNK) issue(c + 3, (c + 3) & (NSTAGE - 1));

        const uint32_t base = sb + HDR + stg * STG_SZ;
        const uint32_t ah_base = base + OFF_AH;
        const uint32_t al_base = base + OFF_AL;
        const uint32_t bh_base = base + OFF_BH;
        const uint32_t bl_base = base + OFF_BL;

        uint32_t ah[2][4], al[2][4];
#pragma unroll
        for (int mt = 0; mt < 2; mt++) {
            uint32_t ao = a_off0 + (uint32_t)(mt * 16 * STRB);
            ldm_x4(ah[mt], ah_base + ao);
            ldm_x4(al[mt], al_base + ao);
        }
        // 7 common n-tiles, fully unrolled
#pragma unroll
        for (int jt = 0; jt < 7; jt++) {
            uint32_t bo = b_off + (uint32_t)(jt * 8 * STRB);
            uint32_t bh0, bh1, bl0, bl1;
            ldm_x2(bh0, bh1, bh_base + bo);
            ldm_x2(bl0, bl1, bl_base + bo);
#pragma unroll
            for (int mt = 0; mt < 2; mt++) {
                mma_bf16(acc[mt][jt], ah[mt], bh0, bh1);   // hi * hi
                mma_bf16(acc[mt][jt], ah[mt], bl0, bl1);   // hi * lo
                mma_bf16(acc[mt][jt], al[mt], bh0, bh1);   // lo * hi
            }
        }
        // 8th tile only for n-warp 0
        if (wn == 0) {
            uint32_t bo = b_off + (uint32_t)(7 * 8 * STRB);
            uint32_t bh0, bh1, bl0, bl1;
            ldm_x2(bh0, bh1, bh_base + bo);
            ldm_x2(bl0, bl1, bl_base + bo);
#pragma unroll
            for (int mt = 0; mt < 2; mt++) {
                mma_bf16(acc[mt][7], ah[mt], bh0, bh1);
                mma_bf16(acc[mt][7], ah[mt], bl0, bl1);
                mma_bf16(acc[mt][7], al[mt], bh0, bh1);
            }
        }
        __syncthreads();
    }

    // --- epilogue: g_part[slot][t][n] = w_t * (acc + bias); plain stores ---
    const int njt = 8 - wn;
    const float* bp = eb + e * DD;
#pragma unroll
    for (int mt = 0; mt < 2; mt++) {
        int r1 = m0w + mt * 16 + (lane >> 2);
        int r2 = r1 + 8;
        int v1 = tsp[r1], v2 = tsp[r2];
        float w1 = wsp[r1], w2 = wsp[r2];
        float* o1 = (v1 < 0) ? nullptr : &g_part[v1 & 1][(size_t)(v1 >> 1) * DD];
        float* o2 = (v2 < 0) ? nullptr : &g_part[v2 & 1][(size_t)(v2 >> 1) * DD];
#pragma unroll
        for (int jt = 0; jt < 8; jt++) {
            if (jt >= njt) break;
            int cc = nb + wn * 64 + jt * 8 + 2 * (lane & 3);
            float b0v = bp[cc], b1v = bp[cc + 1];
            if (o1) {
                o1[cc]     = w1 * (acc[mt][jt][0] + b0v);
                o1[cc + 1] = w1 * (acc[mt][jt][1] + b1v);
            }
            if (o2) {
                o2[cc]     = w2 * (acc[mt][jt][2] + b0v);
                o2[cc + 1] = w2 * (acc[mt][jt][3] + b1v);
            }
        }
    }
}

// ---------------------------------------------------------------------------
// Kernel 5: combine — out = part[0] + part[1]
// ---------------------------------------------------------------------------
__global__ __launch_bounds__(256)
void combine_kernel(float4* __restrict__ out4, int n4) {
    int i = blockIdx.x * blockDim.x + threadIdx.x;
    if (i >= n4) return;
    float4 a = ((const float4*)g_part[0])[i];
    float4 b = ((const float4*)g_part[1])[i];
    out4[i] = make_float4(a.x + b.x, a.y + b.y, a.z + b.z, a.w + b.w);
}

// ---------------------------------------------------------------------------
extern "C" void kernel_launch(void* const* d_in, const int* in_sizes, int n_in,
                              void* d_out, int out_size) {
    const float* x  = (const float*)d_in[0];   // [B,S,D]
    const float* gw = (const float*)d_in[1];   // [E,D]
    const float* gb = (const float*)d_in[2];   // [E]
    const float* ew = (const float*)d_in[3];   // [E,D,D]
    const float* eb = (const float*)d_in[4];   // [E,D]
    float* out = (float*)d_out;                // [B,S,D] fp32

    unsigned short *wh, *wl;
    cudaGetSymbolAddress((void**)&wh, g_wh);
    cudaGetSymbolAddress((void**)&wl, g_wl);

    int nw8 = EE * DD * DD / 8;                // 57600
    conv_kernel<<<(nw8 + 255) / 256, 256>>>(ew, wh, wl, nw8);

    gate_kernel<<<(TT * 32) / 256, 256>>>(x, gw, gb);
    scatter_kernel<<<TT / 256, 256>>>();

    cudaFuncSetAttribute(moe_mma_kernel,
                         cudaFuncAttributeMaxDynamicSharedMemorySize, SMEM_TOT);
    dim3 ggrid(TT / BM, 2, EE);                // (256, 2, 8)
    moe_mma_kernel<<<ggrid, 256, SMEM_TOT>>>(eb);

    int n4 = out_size / 4;                     // 1,966,080
    combine_kernel<<<(n4 + 255) / 256, 256>>>((float4*)out, n4);
}

// round 12
// speedup vs baseline: 2.2213x; 1.0658x over previous
#include <cuda_runtime.h>
#include <cuda_bf16.h>
#include <cstdint>

// Problem constants (fixed by the dataset)
#define BB   16
#define SS   2048
#define DD   240
#define EE   8
#define TT   (BB * SS)        // 32768 tokens

#define KCH     16            // k per chunk (one mma K)
#define NCHUNK  (DD / KCH)    // 15
#define BM      128           // tokens per CTA tile
#define BN      80            // output cols per CTA (grid.y = 3)
#define STRB    48            // smem row stride in BYTES (conflict-free ldmatrix)
#define NSTAGE  3             // cp.async pipeline stages

// ---------------------------------------------------------------------------
// Device-global scratch (no runtime allocation allowed)
// ---------------------------------------------------------------------------
__device__ int   g_cnt[EE];
__device__ int   g_tok[EE][TT];       // packed: (token << 1) | slot
__device__ float g_gw [EE][TT];
__device__ int   g_e1[TT], g_e2[TT];  // per-token top-2 expert ids
__device__ float g_w1[TT], g_w2[TT];  // per-token renormalized weights
__device__ __align__(16) unsigned short g_xh[(size_t)TT * DD];       // bf16 hi of x
__device__ __align__(16) unsigned short g_xl[(size_t)TT * DD];       // bf16 lo of x
__device__ __align__(16) unsigned short g_wh[(size_t)EE * DD * DD];  // bf16 hi of W
__device__ __align__(16) unsigned short g_wl[(size_t)EE * DD * DD];  // bf16 lo of W
__device__ __align__(16) float g_part[2][(size_t)TT * DD];           // per-slot partials

// ---------------------------------------------------------------------------
// PTX helpers
// ---------------------------------------------------------------------------
__device__ __forceinline__ void cp16(uint32_t dst, const void* src, int sz) {
    asm volatile("cp.async.ca.shared.global [%0], [%1], 16, %2;"
                 :: "r"(dst), "l"(src), "r"(sz));
}
#define CP_COMMIT() asm volatile("cp.async.commit_group;")
#define CP_WAIT(n)  asm volatile("cp.async.wait_group %0;" :: "n"(n))

__device__ __forceinline__ void ldm_x4(uint32_t (&r)[4], uint32_t addr) {
    asm volatile("ldmatrix.sync.aligned.m8n8.x4.shared.b16 {%0,%1,%2,%3}, [%4];"
                 : "=r"(r[0]), "=r"(r[1]), "=r"(r[2]), "=r"(r[3]) : "r"(addr));
}
__device__ __forceinline__ void ldm_x2(uint32_t& r0, uint32_t& r1, uint32_t addr) {
    asm volatile("ldmatrix.sync.aligned.m8n8.x2.shared.b16 {%0,%1}, [%2];"
                 : "=r"(r0), "=r"(r1) : "r"(addr));
}
__device__ __forceinline__ void mma_bf16(float (&d)[4], const uint32_t (&a)[4],
                                         uint32_t b0, uint32_t b1) {
    asm volatile("mma.sync.aligned.m16n8k16.row.col.f32.bf16.bf16.f32 "
                 "{%0,%1,%2,%3}, {%4,%5,%6,%7}, {%8,%9}, {%0,%1,%2,%3};"
                 : "+f"(d[0]), "+f"(d[1]), "+f"(d[2]), "+f"(d[3])
                 : "r"(a[0]), "r"(a[1]), "r"(a[2]), "r"(a[3]), "r"(b0), "r"(b1));
}
__device__ __forceinline__ uint32_t smem_u32(const void* p) {
    uint32_t a;
    asm("{ .reg .u64 t; cvta.to.shared.u64 t, %1; cvt.u32.u64 %0, t; }" : "=r"(a) : "l"(p));
    return a;
}

// ---------------------------------------------------------------------------
// Kernel 1: W fp32 -> bf16 (hi, lo) split, 8 elems/thread
// ---------------------------------------------------------------------------
__global__ __launch_bounds__(256)
void conv_kernel(const float* __restrict__ src,
                 unsigned short* __restrict__ dh,
                 unsigned short* __restrict__ dl, int n8) {
    int i = blockIdx.x * blockDim.x + threadIdx.x;
    if (i >= n8) return;
    const float4* s4 = (const float4*)(src + (size_t)i * 8);
    float4 v0 = s4[0], v1 = s4[1];
    float v[8] = {v0.x, v0.y, v0.z, v0.w, v1.x, v1.y, v1.z, v1.w};
    unsigned short h[8], l[8];
#pragma unroll
    for (int j = 0; j < 8; j++) {
        __nv_bfloat16 hi = __float2bfloat16(v[j]);
        __nv_bfloat16 lo = __float2bfloat16(v[j] - __bfloat162float(hi));
        h[j] = *(unsigned short*)&hi;
        l[j] = *(unsigned short*)&lo;
    }
    *(uint4*)(dh + (size_t)i * 8) = *(uint4*)h;
    *(uint4*)(dl + (size_t)i * 8) = *(uint4*)l;
}

// ---------------------------------------------------------------------------
// Kernel 2: gating — one warp per token; dense top-2 outputs, folded x->bf16
// hi/lo conversion. No contended atomics.
// ---------------------------------------------------------------------------
__global__ __launch_bounds__(256)
void gate_kernel(const float* __restrict__ x,
                 const float* __restrict__ gw,
                 const float* __restrict__ gb) {
    if (blockIdx.x == 0 && threadIdx.x < EE) g_cnt[threadIdx.x] = 0;

    int warp = (blockIdx.x * blockDim.x + threadIdx.x) >> 5;
    int lane = threadIdx.x & 31;
    if (warp >= TT) return;

    const float* xp = x + (long)warp * DD;
    float xv[8];
#pragma unroll
    for (int i = 0; i < 8; i++) {
        int d = lane + 32 * i;
        xv[i] = (d < DD) ? xp[d] : 0.f;
    }

#pragma unroll
    for (int i = 0; i < 8; i++) {
        int d = lane + 32 * i;
        if (d < DD) {
            __nv_bfloat16 hi = __float2bfloat16(xv[i]);
            __nv_bfloat16 lo = __float2bfloat16(xv[i] - __bfloat162float(hi));
            g_xh[(size_t)warp * DD + d] = *(unsigned short*)&hi;
            g_xl[(size_t)warp * DD + d] = *(unsigned short*)&lo;
        }
    }

    float l[EE];
#pragma unroll
    for (int e = 0; e < EE; e++) {
        const float* wp = gw + e * DD;
        float s = 0.f;
#pragma unroll
        for (int i = 0; i < 8; i++) {
            int d = lane + 32 * i;
            s += xv[i] * ((d < DD) ? wp[d] : 0.f);
        }
#pragma unroll
        for (int o = 16; o > 0; o >>= 1) s += __shfl_xor_sync(0xffffffffu, s, o);
        l[e] = s + gb[e];
    }

    if (lane == 0) {
        int b1 = 0;
#pragma unroll
        for (int e = 1; e < EE; e++) if (l[e] > l[b1]) b1 = e;
        int b2 = (b1 == 0) ? 1 : 0;
#pragma unroll
        for (int e = 0; e < EE; e++) {
            if (e == b1 || e == b2) continue;
            if (l[e] > l[b2]) b2 = e;
        }
        float m  = fmaxf(l[b1], l[b2]);
        float e1 = __expf(l[b1] - m);
        float e2 = __expf(l[b2] - m);
        float inv = 1.f / (e1 + e2);
        g_e1[warp] = b1;  g_w1[warp] = e1 * inv;
        g_e2[warp] = b2;  g_w2[warp] = e2 * inv;
    }
}

// ---------------------------------------------------------------------------
// Kernel 3: scatter — warp-aggregated atomics; packs (token<<1)|slot.
// ---------------------------------------------------------------------------
__global__ __launch_bounds__(256)
void scatter_kernel() {
    int t = blockIdx.x * blockDim.x + threadIdx.x;
    if (t >= TT) return;
    int lane = threadIdx.x & 31;
#pragma unroll
    for (int slot = 0; slot < 2; slot++) {
        int   e = slot ? g_e2[t] : g_e1[t];
        float w = slot ? g_w2[t] : g_w1[t];
        unsigned mask = __match_any_sync(0xffffffffu, e);
        int leader = __ffs(mask) - 1;
        int rank   = __popc(mask & ((1u << lane) - 1));
        int base = 0;
        if (lane == leader) base = atomicAdd(&g_cnt[e], __popc(mask));
        base = __shfl_sync(mask, base, leader);
        int pos = base + rank;
        g_tok[e][pos] = (t << 1) | slot;
        g_gw [e][pos] = w;
    }
}

// ---------------------------------------------------------------------------
// Kernel 4: grouped expert GEMM on warp tensor cores (bf16 split, 3 terms).
// grid = (TT/BM, 3, E). 128 threads = 4 m-warps x 1 n-warp (warp tile 32x80).
// All 4 warps share one 80-col B tile; 3-stage cp.async pipeline with ONE
// __syncthreads per chunk. Epilogue: plain stores into g_part — NO atomics.
// ---------------------------------------------------------------------------
#define HDR     1024
#define A_SZ    (BM * STRB)            // 6144 B per (hi|lo) A stage part
#define B_SZ    (BN * STRB)            // 3840 B per (hi|lo) B stage part
#define STG_SZ  (2 * A_SZ + 2 * B_SZ)  // 19968 B per stage
#define OFF_AH  0
#define OFF_AL  A_SZ
#define OFF_BH  (2 * A_SZ)
#define OFF_BL  (2 * A_SZ + B_SZ)
#define SMEM_TOT (HDR + NSTAGE * STG_SZ)   // 60928 B -> 3 CTAs/SM

__global__ __launch_bounds__(128, 3)
void moe_mma_kernel(const float* __restrict__ eb) {
    const int e   = blockIdx.z;
    const int cnt = g_cnt[e];
    const int m0  = blockIdx.x * BM;
    if (m0 >= cnt) return;
    const int nb  = blockIdx.y * BN;      // 0, 80, 160

    extern __shared__ __align__(16) char smem[];
    int*   tsp = (int*)  smem;
    float* wsp = (float*)(smem + 512);
    const uint32_t sb = smem_u32(smem);

    const int tid  = threadIdx.x;
    const int lane = tid & 31;
    const int wid  = tid >> 5;           // m-warp 0..3
    const int m0w  = wid * 32;

    if (tid < BM) {
        int gr = m0 + tid;
        if (gr < cnt) { tsp[tid] = g_tok[e][gr]; wsp[tid] = g_gw[e][gr]; }
        else          { tsp[tid] = -1;           wsp[tid] = 0.f; }
    }
    __syncthreads();

    // --- cp.async issue for chunk c into stage stg ---
    auto issue = [&](int c, int stg) {
        uint32_t base = sb + HDR + stg * STG_SZ;
        // A: 128 rows x 2 segs of 16B = 256; 128 threads x 2 rounds (hi + lo)
#pragma unroll
        for (int s = tid; s < BM * 2; s += 128) {
            int row = s >> 1, h = s & 1;
            int v = tsp[row];
            size_t so = (size_t)((v < 0) ? 0 : (v >> 1)) * DD + c * KCH + h * 8;
            int  sz = (v >= 0) ? 16 : 0;
            uint32_t d = (uint32_t)(row * STRB + h * 16);
            cp16(base + OFF_AH + d, g_xh + so, sz);
            cp16(base + OFF_AL + d, g_xl + so, sz);
        }
        // B: 80 rows x 2 segs = 160; threads 0..127 + 0..31 second round
#pragma unroll
        for (int s = tid; s < BN * 2; s += 128) {
            int row = s >> 1, h = s & 1;
            size_t so = ((size_t)e * DD + nb + row) * DD + c * KCH + h * 8;
            uint32_t d = (uint32_t)(row * STRB + h * 16);
            cp16(base + OFF_BH + d, g_wh + so, 16);
            cp16(base + OFF_BL + d, g_wl + so, 16);
        }
        CP_COMMIT();
    };

    // ldmatrix lane byte offsets (48B row stride), fixed across chunks
    const uint32_t a_off0 = (uint32_t)((m0w + (lane & 15)) * STRB + ((lane >> 4) << 4));
    const int      l16    = lane & 15;
    const uint32_t b_off  = (uint32_t)((l16 & 7) * STRB + ((l16 >> 3) << 4));

    float acc[2][10][4] = {};

    issue(0, 0);
    issue(1, 1);

    for (int c = 0; c < NCHUNK; c++) {
        const int stg = (c < 15) ? (c % NSTAGE) : 0;
        if (c < NCHUNK - 1) CP_WAIT(1); else CP_WAIT(0);
        __syncthreads();        // stage c ready for all; all done with c-1

        if (c + 2 < NCHUNK) issue(c + 2, (c + 2) % NSTAGE);

        const uint32_t base = sb + HDR + stg * STG_SZ;
        const uint32_t ah_base = base + OFF_AH;
        const uint32_t al_base = base + OFF_AL;
        const uint32_t bh_base = base + OFF_BH;
        const uint32_t bl_base = base + OFF_BL;

        uint32_t ah[2][4], al[2][4];
#pragma unroll
        for (int mt = 0; mt < 2; mt++) {
            uint32_t ao = a_off0 + (uint32_t)(mt * 16 * STRB);
            ldm_x4(ah[mt], ah_base + ao);
            ldm_x4(al[mt], al_base + ao);
        }
#pragma unroll
        for (int jt = 0; jt < 10; jt++) {
            uint32_t bo = b_off + (uint32_t)(jt * 8 * STRB);
            uint32_t bh0, bh1, bl0, bl1;
            ldm_x2(bh0, bh1, bh_base + bo);
            ldm_x2(bl0, bl1, bl_base + bo);
#pragma unroll
            for (int mt = 0; mt < 2; mt++) {
                mma_bf16(acc[mt][jt], ah[mt], bh0, bh1);   // hi * hi
                mma_bf16(acc[mt][jt], ah[mt], bl0, bl1);   // hi * lo
                mma_bf16(acc[mt][jt], al[mt], bh0, bh1);   // lo * hi
            }
        }
    }

    // --- epilogue: g_part[slot][t][n] = w_t * (acc + bias); plain stores ---
    const float* bp = eb + e * DD;
#pragma unroll
    for (int mt = 0; mt < 2; mt++) {
        int r1 = m0w + mt * 16 + (lane >> 2);
        int r2 = r1 + 8;
        int v1 = tsp[r1], v2 = tsp[r2];
        float w1 = wsp[r1], w2 = wsp[r2];
        float* o1 = (v1 < 0) ? nullptr : &g_part[v1 & 1][(size_t)(v1 >> 1) * DD];
        float* o2 = (v2 < 0) ? nullptr : &g_part[v2 & 1][(size_t)(v2 >> 1) * DD];
#pragma unroll
        for (int jt = 0; jt < 10; jt++) {
            int cc = nb + jt * 8 + 2 * (lane & 3);
            float b0v = bp[cc], b1v = bp[cc + 1];
            if (o1) {
                o1[cc]     = w1 * (acc[mt][jt][0] + b0v);
                o1[cc + 1] = w1 * (acc[mt][jt][1] + b1v);
            }
            if (o2) {
                o2[cc]     = w2 * (acc[mt][jt][2] + b0v);
                o2[cc + 1] = w2 * (acc[mt][jt][3] + b1v);
            }
        }
    }
}

// ---------------------------------------------------------------------------
// Kernel 5: combine — out = part[0] + part[1]
// ---------------------------------------------------------------------------
__global__ __launch_bounds__(256)
void combine_kernel(float4* __restrict__ out4, int n4) {
    int i = blockIdx.x * blockDim.x + threadIdx.x;
    if (i >= n4) return;
    float4 a = ((const float4*)g_part[0])[i];
    float4 b = ((const float4*)g_part[1])[i];
    out4[i] = make_float4(a.x + b.x, a.y + b.y, a.z + b.z, a.w + b.w);
}

// ---------------------------------------------------------------------------
extern "C" void kernel_launch(void* const* d_in, const int* in_sizes, int n_in,
                              void* d_out, int out_size) {
    const float* x  = (const float*)d_in[0];   // [B,S,D]
    const float* gw = (const float*)d_in[1];   // [E,D]
    const float* gb = (const float*)d_in[2];   // [E]
    const float* ew = (const float*)d_in[3];   // [E,D,D]
    const float* eb = (const float*)d_in[4];   // [E,D]
    float* out = (float*)d_out;                // [B,S,D] fp32

    unsigned short *wh, *wl;
    cudaGetSymbolAddress((void**)&wh, g_wh);
    cudaGetSymbolAddress((void**)&wl, g_wl);

    int nw8 = EE * DD * DD / 8;                // 57600
    conv_kernel<<<(nw8 + 255) / 256, 256>>>(ew, wh, wl, nw8);

    gate_kernel<<<(TT * 32) / 256, 256>>>(x, gw, gb);
    scatter_kernel<<<TT / 256, 256>>>();

    cudaFuncSetAttribute(moe_mma_kernel,
                         cudaFuncAttributeMaxDynamicSharedMemorySize, SMEM_TOT);
    dim3 ggrid(TT / BM, 3, EE);                // (256, 3, 8)
    moe_mma_kernel<<<ggrid, 128, SMEM_TOT>>>(eb);

    int n4 = out_size / 4;                     // 1,966,080
    combine_kernel<<<(n4 + 255) / 256, 256>>>((float4*)out, n4);
}

// round 13
// speedup vs baseline: 2.2637x; 1.0191x over previous
#include <cuda_runtime.h>
#include <cuda_bf16.h>
#include <cstdint>

// Problem constants (fixed by the dataset)
#define BB   16
#define SS   2048
#define DD   240
#define EE   8
#define TT   (BB * SS)        // 32768 tokens

#define KCH     16            // k per chunk (one mma K)
#define NCHUNK  (DD / KCH)    // 15
#define BM      128           // tokens per CTA tile
#define BN      80            // output cols per CTA (grid.y = 3)
#define STRB    48            // smem row stride in BYTES (conflict-free ldmatrix)
#define NSTAGE  3             // cp.async pipeline stages

// ---------------------------------------------------------------------------
// Device-global scratch (no runtime allocation allowed)
// ---------------------------------------------------------------------------
__device__ int   g_cnt[EE];
__device__ int   g_tok[EE][TT];       // packed: (token << 1) | slot
__device__ float g_gw [EE][TT];
__device__ int   g_e1[TT], g_e2[TT];  // per-token top-2 expert ids
__device__ float g_w1[TT], g_w2[TT];  // per-token renormalized weights
__device__ __align__(16) unsigned short g_xh[(size_t)TT * DD];       // bf16 hi of x
__device__ __align__(16) unsigned short g_xl[(size_t)TT * DD];       // bf16 lo of x
__device__ __align__(16) unsigned short g_wh[(size_t)EE * DD * DD];  // bf16 hi of W
__device__ __align__(16) unsigned short g_wl[(size_t)EE * DD * DD];  // bf16 lo of W
__device__ __align__(16) float g_part[2][(size_t)TT * DD];           // per-slot partials

// ---------------------------------------------------------------------------
// PTX helpers
// ---------------------------------------------------------------------------
__device__ __forceinline__ void cp16(uint32_t dst, const void* src, int sz) {
    asm volatile("cp.async.ca.shared.global [%0], [%1], 16, %2;"
                 :: "r"(dst), "l"(src), "r"(sz));
}
#define CP_COMMIT() asm volatile("cp.async.commit_group;")
#define CP_WAIT(n)  asm volatile("cp.async.wait_group %0;" :: "n"(n))

__device__ __forceinline__ void ldm_x4(uint32_t (&r)[4], uint32_t addr) {
    asm volatile("ldmatrix.sync.aligned.m8n8.x4.shared.b16 {%0,%1,%2,%3}, [%4];"
                 : "=r"(r[0]), "=r"(r[1]), "=r"(r[2]), "=r"(r[3]) : "r"(addr));
}
__device__ __forceinline__ void mma_bf16(float (&d)[4], const uint32_t (&a)[4],
                                         uint32_t b0, uint32_t b1) {
    asm volatile("mma.sync.aligned.m16n8k16.row.col.f32.bf16.bf16.f32 "
                 "{%0,%1,%2,%3}, {%4,%5,%6,%7}, {%8,%9}, {%0,%1,%2,%3};"
                 : "+f"(d[0]), "+f"(d[1]), "+f"(d[2]), "+f"(d[3])
                 : "r"(a[0]), "r"(a[1]), "r"(a[2]), "r"(a[3]), "r"(b0), "r"(b1));
}
__device__ __forceinline__ uint32_t smem_u32(const void* p) {
    uint32_t a;
    asm("{ .reg .u64 t; cvta.to.shared.u64 t, %1; cvt.u32.u64 %0, t; }" : "=r"(a) : "l"(p));
    return a;
}

// ---------------------------------------------------------------------------
// Kernel 1: W fp32 -> bf16 (hi, lo) split, 8 elems/thread
// ---------------------------------------------------------------------------
__global__ __launch_bounds__(256)
void conv_kernel(const float* __restrict__ src,
                 unsigned short* __restrict__ dh,
                 unsigned short* __restrict__ dl, int n8) {
    int i = blockIdx.x * blockDim.x + threadIdx.x;
    if (i >= n8) return;
    const float4* s4 = (const float4*)(src + (size_t)i * 8);
    float4 v0 = s4[0], v1 = s4[1];
    float v[8] = {v0.x, v0.y, v0.z, v0.w, v1.x, v1.y, v1.z, v1.w};
    unsigned short h[8], l[8];
#pragma unroll
    for (int j = 0; j < 8; j++) {
        __nv_bfloat16 hi = __float2bfloat16(v[j]);
        __nv_bfloat16 lo = __float2bfloat16(v[j] - __bfloat162float(hi));
        h[j] = *(unsigned short*)&hi;
        l[j] = *(unsigned short*)&lo;
    }
    *(uint4*)(dh + (size_t)i * 8) = *(uint4*)h;
    *(uint4*)(dl + (size_t)i * 8) = *(uint4*)l;
}

// ---------------------------------------------------------------------------
// Kernel 2: gating — one warp per token; dense top-2 outputs, folded x->bf16
// hi/lo conversion. No contended atomics.
// ---------------------------------------------------------------------------
__global__ __launch_bounds__(256)
void gate_kernel(const float* __restrict__ x,
                 const float* __restrict__ gw,
                 const float* __restrict__ gb) {
    if (blockIdx.x == 0 && threadIdx.x < EE) g_cnt[threadIdx.x] = 0;

    int warp = (blockIdx.x * blockDim.x + threadIdx.x) >> 5;
    int lane = threadIdx.x & 31;
    if (warp >= TT) return;

    const float* xp = x + (long)warp * DD;
    float xv[8];
#pragma unroll
    for (int i = 0; i < 8; i++) {
        int d = lane + 32 * i;
        xv[i] = (d < DD) ? xp[d] : 0.f;
    }

#pragma unroll
    for (int i = 0; i < 8; i++) {
        int d = lane + 32 * i;
        if (d < DD) {
            __nv_bfloat16 hi = __float2bfloat16(xv[i]);
            __nv_bfloat16 lo = __float2bfloat16(xv[i] - __bfloat162float(hi));
            g_xh[(size_t)warp * DD + d] = *(unsigned short*)&hi;
            g_xl[(size_t)warp * DD + d] = *(unsigned short*)&lo;
        }
    }

    float l[EE];
#pragma unroll
    for (int e = 0; e < EE; e++) {
        const float* wp = gw + e * DD;
        float s = 0.f;
#pragma unroll
        for (int i = 0; i < 8; i++) {
            int d = lane + 32 * i;
            s += xv[i] * ((d < DD) ? wp[d] : 0.f);
        }
#pragma unroll
        for (int o = 16; o > 0; o >>= 1) s += __shfl_xor_sync(0xffffffffu, s, o);
        l[e] = s + gb[e];
    }

    if (lane == 0) {
        int b1 = 0;
#pragma unroll
        for (int e = 1; e < EE; e++) if (l[e] > l[b1]) b1 = e;
        int b2 = (b1 == 0) ? 1 : 0;
#pragma unroll
        for (int e = 0; e < EE; e++) {
            if (e == b1 || e == b2) continue;
            if (l[e] > l[b2]) b2 = e;
        }
        float m  = fmaxf(l[b1], l[b2]);
        float e1 = __expf(l[b1] - m);
        float e2 = __expf(l[b2] - m);
        float inv = 1.f / (e1 + e2);
        g_e1[warp] = b1;  g_w1[warp] = e1 * inv;
        g_e2[warp] = b2;  g_w2[warp] = e2 * inv;
    }
}

// ---------------------------------------------------------------------------
// Kernel 3: scatter — warp-aggregated atomics; packs (token<<1)|slot.
// ---------------------------------------------------------------------------
__global__ __launch_bounds__(256)
void scatter_kernel() {
    int t = blockIdx.x * blockDim.x + threadIdx.x;
    if (t >= TT) return;
    int lane = threadIdx.x & 31;
#pragma unroll
    for (int slot = 0; slot < 2; slot++) {
        int   e = slot ? g_e2[t] : g_e1[t];
        float w = slot ? g_w2[t] : g_w1[t];
        unsigned mask = __match_any_sync(0xffffffffu, e);
        int leader = __ffs(mask) - 1;
        int rank   = __popc(mask & ((1u << lane) - 1));
        int base = 0;
        if (lane == leader) base = atomicAdd(&g_cnt[e], __popc(mask));
        base = __shfl_sync(mask, base, leader);
        int pos = base + rank;
        g_tok[e][pos] = (t << 1) | slot;
        g_gw [e][pos] = w;
    }
}

// ---------------------------------------------------------------------------
// Kernel 4: grouped expert GEMM on warp tensor cores (bf16 split, 3 terms).
// grid = (TT/BM, 3, E). 128 threads = 4 m-warps x 1 n-warp (warp tile 32x80).
// B fragments loaded as jt-PAIRS via ldm_x4 (half the LDSM ops of ldm_x2);
// 12-HMMA interleaved schedule per pair -> dep distance 4 between same-acc
// HMMAs. 3-stage cp.async pipeline, one __syncthreads per chunk.
// ---------------------------------------------------------------------------
#define HDR     1024
#define A_SZ    (BM * STRB)            // 6144 B per (hi|lo) A stage part
#define B_SZ    (BN * STRB)            // 3840 B per (hi|lo) B stage part
#define STG_SZ  (2 * A_SZ + 2 * B_SZ)  // 19968 B per stage
#define OFF_AH  0
#define OFF_AL  A_SZ
#define OFF_BH  (2 * A_SZ)
#define OFF_BL  (2 * A_SZ + B_SZ)
#define SMEM_TOT (HDR + NSTAGE * STG_SZ)   // 60928 B -> 3 CTAs/SM

__global__ __launch_bounds__(128, 3)
void moe_mma_kernel(const float* __restrict__ eb) {
    const int e   = blockIdx.z;
    const int cnt = g_cnt[e];
    const int m0  = blockIdx.x * BM;
    if (m0 >= cnt) return;
    const int nb  = blockIdx.y * BN;      // 0, 80, 160

    extern __shared__ __align__(16) char smem[];
    int*   tsp = (int*)  smem;
    float* wsp = (float*)(smem + 512);
    const uint32_t sb = smem_u32(smem);

    const int tid  = threadIdx.x;
    const int lane = tid & 31;
    const int wid  = tid >> 5;           // m-warp 0..3
    const int m0w  = wid * 32;

    if (tid < BM) {
        int gr = m0 + tid;
        if (gr < cnt) { tsp[tid] = g_tok[e][gr]; wsp[tid] = g_gw[e][gr]; }
        else          { tsp[tid] = -1;           wsp[tid] = 0.f; }
    }
    __syncthreads();

    // --- cp.async issue for chunk c into stage stg ---
    auto issue = [&](int c, int stg) {
        uint32_t base = sb + HDR + stg * STG_SZ;
        // A: 128 rows x 2 segs of 16B = 256; 128 threads x 2 rounds (hi + lo)
#pragma unroll
        for (int s = tid; s < BM * 2; s += 128) {
            int row = s >> 1, h = s & 1;
            int v = tsp[row];
            size_t so = (size_t)((v < 0) ? 0 : (v >> 1)) * DD + c * KCH + h * 8;
            int  sz = (v >= 0) ? 16 : 0;
            uint32_t d = (uint32_t)(row * STRB + h * 16);
            cp16(base + OFF_AH + d, g_xh + so, sz);
            cp16(base + OFF_AL + d, g_xl + so, sz);
        }
        // B: 80 rows x 2 segs = 160
#pragma unroll
        for (int s = tid; s < BN * 2; s += 128) {
            int row = s >> 1, h = s & 1;
            size_t so = ((size_t)e * DD + nb + row) * DD + c * KCH + h * 8;
            uint32_t d = (uint32_t)(row * STRB + h * 16);
            cp16(base + OFF_BH + d, g_wh + so, 16);
            cp16(base + OFF_BL + d, g_wl + so, 16);
        }
        CP_COMMIT();
    };

    // ldmatrix lane byte offsets (48B row stride), fixed across chunks
    const uint32_t a_off0 = (uint32_t)((m0w + (lane & 15)) * STRB + ((lane >> 4) << 4));
    // B pair-x4: lanes 0-7 -> rows r0..r0+7 khalf0, 8-15 -> khalf1,
    //            16-23 -> rows r0+8.., 24-31 -> khalf1
    const uint32_t b_off0 = (uint32_t)(((lane & 7) + ((lane >> 4) << 3)) * STRB
                                       + (((lane >> 3) & 1) << 4));

    float acc[2][10][4] = {};

    issue(0, 0);
    issue(1, 1);

    for (int c = 0; c < NCHUNK; c++) {
        const int stg = c % NSTAGE;
        if (c < NCHUNK - 1) CP_WAIT(1); else CP_WAIT(0);
        __syncthreads();        // stage c ready for all; all done with c-1

        if (c + 2 < NCHUNK) issue(c + 2, (c + 2) % NSTAGE);

        const uint32_t base = sb + HDR + stg * STG_SZ;
        const uint32_t ah_base = base + OFF_AH;
        const uint32_t al_base = base + OFF_AL;
        const uint32_t bh_base = base + OFF_BH + b_off0;
        const uint32_t bl_base = base + OFF_BL + b_off0;

        uint32_t ah[2][4], al[2][4];
#pragma unroll
        for (int mt = 0; mt < 2; mt++) {
            uint32_t ao = a_off0 + (uint32_t)(mt * 16 * STRB);
            ldm_x4(ah[mt], ah_base + ao);
            ldm_x4(al[mt], al_base + ao);
        }
#pragma unroll
        for (int jp = 0; jp < 5; jp++) {
            const int j0 = 2 * jp, j1 = 2 * jp + 1;
            const uint32_t po = (uint32_t)(jp * 16 * STRB);
            uint32_t bh[4], bl[4];
            ldm_x4(bh, bh_base + po);      // {b0,b1}(j0), {b0,b1}(j1) hi
            ldm_x4(bl, bl_base + po);      // same, lo
            // 12 HMMAs, interleaved: same-acc dep distance = 4
            mma_bf16(acc[0][j0], ah[0], bh[0], bh[1]);
            mma_bf16(acc[1][j0], ah[1], bh[0], bh[1]);
            mma_bf16(acc[0][j1], ah[0], bh[2], bh[3]);
            mma_bf16(acc[1][j1], ah[1], bh[2], bh[3]);
            mma_bf16(acc[0][j0], ah[0], bl[0], bl[1]);
            mma_bf16(acc[1][j0], ah[1], bl[0], bl[1]);
            mma_bf16(acc[0][j1], ah[0], bl[2], bl[3]);
            mma_bf16(acc[1][j1], ah[1], bl[2], bl[3]);
            mma_bf16(acc[0][j0], al[0], bh[0], bh[1]);
            mma_bf16(acc[1][j0], al[1], bh[0], bh[1]);
            mma_bf16(acc[0][j1], al[0], bh[2], bh[3]);
            mma_bf16(acc[1][j1], al[1], bh[2], bh[3]);
        }
    }

    // --- epilogue: g_part[slot][t][n] = w_t * (acc + bias); plain stores ---
    const float* bp = eb + e * DD;
#pragma unroll
    for (int mt = 0; mt < 2; mt++) {
        int r1 = m0w + mt * 16 + (lane >> 2);
        int r2 = r1 + 8;
        int v1 = tsp[r1], v2 = tsp[r2];
        float w1 = wsp[r1], w2 = wsp[r2];
        float* o1 = (v1 < 0) ? nullptr : &g_part[v1 & 1][(size_t)(v1 >> 1) * DD];
        float* o2 = (v2 < 0) ? nullptr : &g_part[v2 & 1][(size_t)(v2 >> 1) * DD];
#pragma unroll
        for (int jt = 0; jt < 10; jt++) {
            int cc = nb + jt * 8 + 2 * (lane & 3);
            float b0v = bp[cc], b1v = bp[cc + 1];
            if (o1) {
                o1[cc]     = w1 * (acc[mt][jt][0] + b0v);
                o1[cc + 1] = w1 * (acc[mt][jt][1] + b1v);
            }
            if (o2) {
                o2[cc]     = w2 * (acc[mt][jt][2] + b0v);
                o2[cc + 1] = w2 * (acc[mt][jt][3] + b1v);
            }
        }
    }
}

// ---------------------------------------------------------------------------
// Kernel 5: combine — out = part[0] + part[1]
// ---------------------------------------------------------------------------
__global__ __launch_bounds__(256)
void combine_kernel(float4* __restrict__ out4, int n4) {
    int i = blockIdx.x * blockDim.x + threadIdx.x;
    if (i >= n4) return;
    float4 a = ((const float4*)g_part[0])[i];
    float4 b = ((const float4*)g_part[1])[i];
    out4[i] = make_float4(a.x + b.x, a.y + b.y, a.z + b.z, a.w + b.w);
}

// ---------------------------------------------------------------------------
extern "C" void kernel_launch(void* const* d_in, const int* in_sizes, int n_in,
                              void* d_out, int out_size) {
    const float* x  = (const float*)d_in[0];   // [B,S,D]
    const float* gw = (const float*)d_in[1];   // [E,D]
    const float* gb = (const float*)d_in[2];   // [E]
    const float* ew = (const float*)d_in[3];   // [E,D,D]
    const float* eb = (const float*)d_in[4];   // [E,D]
    float* out = (float*)d_out;                // [B,S,D] fp32

    unsigned short *wh, *wl;
    cudaGetSymbolAddress((void**)&wh, g_wh);
    cudaGetSymbolAddress((void**)&wl, g_wl);

    int nw8 = EE * DD * DD / 8;                // 57600
    conv_kernel<<<(nw8 + 255) / 256, 256>>>(ew, wh, wl, nw8);

    gate_kernel<<<(TT * 32) / 256, 256>>>(x, gw, gb);
    scatter_kernel<<<TT / 256, 256>>>();

    cudaFuncSetAttribute(moe_mma_kernel,
                         cudaFuncAttributeMaxDynamicSharedMemorySize, SMEM_TOT);
    dim3 ggrid(TT / BM, 3, EE);                // (256, 3, 8)
    moe_mma_kernel<<<ggrid, 128, SMEM_TOT>>>(eb);

    int n4 = out_size / 4;                     // 1,966,080
    combine_kernel<<<(n4 + 255) / 256, 256>>>((float4*)out, n4);
}

// round 14
// speedup vs baseline: 3.1470x; 1.3902x over previous
#include <cuda_runtime.h>
#include <cuda_fp16.h>
#include <cuda_bf16.h>
#include <cstdint>

// Problem constants (fixed by the dataset)
#define BB   16
#define SS   2048
#define DD   240
#define EE   8
#define TT   (BB * SS)        // 32768 tokens

#define KCH     16            // k per chunk (one mma K)
#define NCHUNK  (DD / KCH)    // 15
#define BM      128           // tokens per CTA tile
#define BN      80            // output cols per CTA (grid.y = 3)
#define STRB    48            // smem row stride in BYTES (conflict-free ldmatrix)
#define NSTAGE  4             // cp.async pipeline stages

// ---------------------------------------------------------------------------
// Device-global scratch (no runtime allocation allowed)
// ---------------------------------------------------------------------------
__device__ int   g_cnt[EE];
__device__ int   g_tok[EE][TT];       // packed: (token << 1) | slot
__device__ float g_gw [EE][TT];
__device__ int   g_e1[TT], g_e2[TT];  // per-token top-2 expert ids
__device__ float g_w1[TT], g_w2[TT];  // per-token renormalized weights
__device__ __align__(16) unsigned short g_xf[(size_t)TT * DD];       // fp16 x
__device__ __align__(16) unsigned short g_wf[(size_t)EE * DD * DD];  // fp16 W
__device__ __align__(16) float g_part[2][(size_t)TT * DD];           // per-slot partials

// ---------------------------------------------------------------------------
// PTX helpers
// ---------------------------------------------------------------------------
__device__ __forceinline__ void cp16(uint32_t dst, const void* src, int sz) {
    asm volatile("cp.async.ca.shared.global [%0], [%1], 16, %2;"
                 :: "r"(dst), "l"(src), "r"(sz));
}
#define CP_COMMIT() asm volatile("cp.async.commit_group;")
#define CP_WAIT(n)  asm volatile("cp.async.wait_group %0;" :: "n"(n))

__device__ __forceinline__ void ldm_x4(uint32_t (&r)[4], uint32_t addr) {
    asm volatile("ldmatrix.sync.aligned.m8n8.x4.shared.b16 {%0,%1,%2,%3}, [%4];"
                 : "=r"(r[0]), "=r"(r[1]), "=r"(r[2]), "=r"(r[3]) : "r"(addr));
}
__device__ __forceinline__ void mma_fp16(float (&d)[4], const uint32_t (&a)[4],
                                         uint32_t b0, uint32_t b1) {
    asm volatile("mma.sync.aligned.m16n8k16.row.col.f32.f16.f16.f32 "
                 "{%0,%1,%2,%3}, {%4,%5,%6,%7}, {%8,%9}, {%0,%1,%2,%3};"
                 : "+f"(d[0]), "+f"(d[1]), "+f"(d[2]), "+f"(d[3])
                 : "r"(a[0]), "r"(a[1]), "r"(a[2]), "r"(a[3]), "r"(b0), "r"(b1));
}
__device__ __forceinline__ uint32_t smem_u32(const void* p) {
    uint32_t a;
    asm("{ .reg .u64 t; cvta.to.shared.u64 t, %1; cvt.u32.u64 %0, t; }" : "=r"(a) : "l"(p));
    return a;
}

// ---------------------------------------------------------------------------
// Kernel 1: W fp32 -> fp16, 8 elems/thread
// ---------------------------------------------------------------------------
__global__ __launch_bounds__(256)
void conv_kernel(const float* __restrict__ src,
                 unsigned short* __restrict__ df, int n8) {
    int i = blockIdx.x * blockDim.x + threadIdx.x;
    if (i >= n8) return;
    const float4* s4 = (const float4*)(src + (size_t)i * 8);
    float4 v0 = s4[0], v1 = s4[1];
    float v[8] = {v0.x, v0.y, v0.z, v0.w, v1.x, v1.y, v1.z, v1.w};
    unsigned short h[8];
#pragma unroll
    for (int j = 0; j < 8; j++) {
        __half hv = __float2half_rn(v[j]);
        h[j] = *(unsigned short*)&hv;
    }
    *(uint4*)(df + (size_t)i * 8) = *(uint4*)h;
}

// ---------------------------------------------------------------------------
// Kernel 2: gating — one warp per token; dense top-2 outputs, folded x->fp16
// conversion. No contended atomics.
// ---------------------------------------------------------------------------
__global__ __launch_bounds__(256)
void gate_kernel(const float* __restrict__ x,
                 const float* __restrict__ gw,
                 const float* __restrict__ gb) {
    if (blockIdx.x == 0 && threadIdx.x < EE) g_cnt[threadIdx.x] = 0;

    int warp = (blockIdx.x * blockDim.x + threadIdx.x) >> 5;
    int lane = threadIdx.x & 31;
    if (warp >= TT) return;

    const float* xp = x + (long)warp * DD;
    float xv[8];
#pragma unroll
    for (int i = 0; i < 8; i++) {
        int d = lane + 32 * i;
        xv[i] = (d < DD) ? xp[d] : 0.f;
    }

#pragma unroll
    for (int i = 0; i < 8; i++) {
        int d = lane + 32 * i;
        if (d < DD) {
            __half hv = __float2half_rn(xv[i]);
            g_xf[(size_t)warp * DD + d] = *(unsigned short*)&hv;
        }
    }

    float l[EE];
#pragma unroll
    for (int e = 0; e < EE; e++) {
        const float* wp = gw + e * DD;
        float s = 0.f;
#pragma unroll
        for (int i = 0; i < 8; i++) {
            int d = lane + 32 * i;
            s += xv[i] * ((d < DD) ? wp[d] : 0.f);
        }
#pragma unroll
        for (int o = 16; o > 0; o >>= 1) s += __shfl_xor_sync(0xffffffffu, s, o);
        l[e] = s + gb[e];
    }

    if (lane == 0) {
        int b1 = 0;
#pragma unroll
        for (int e = 1; e < EE; e++) if (l[e] > l[b1]) b1 = e;
        int b2 = (b1 == 0) ? 1 : 0;
#pragma unroll
        for (int e = 0; e < EE; e++) {
            if (e == b1 || e == b2) continue;
            if (l[e] > l[b2]) b2 = e;
        }
        float m  = fmaxf(l[b1], l[b2]);
        float e1 = __expf(l[b1] - m);
        float e2 = __expf(l[b2] - m);
        float inv = 1.f / (e1 + e2);
        g_e1[warp] = b1;  g_w1[warp] = e1 * inv;
        g_e2[warp] = b2;  g_w2[warp] = e2 * inv;
    }
}

// ---------------------------------------------------------------------------
// Kernel 3: scatter — warp-aggregated atomics; packs (token<<1)|slot.
// ---------------------------------------------------------------------------
__global__ __launch_bounds__(256)
void scatter_kernel() {
    int t = blockIdx.x * blockDim.x + threadIdx.x;
    if (t >= TT) return;
    int lane = threadIdx.x & 31;
#pragma unroll
    for (int slot = 0; slot < 2; slot++) {
        int   e = slot ? g_e2[t] : g_e1[t];
        float w = slot ? g_w2[t] : g_w1[t];
        unsigned mask = __match_any_sync(0xffffffffu, e);
        int leader = __ffs(mask) - 1;
        int rank   = __popc(mask & ((1u << lane) - 1));
        int base = 0;
        if (lane == leader) base = atomicAdd(&g_cnt[e], __popc(mask));
        base = __shfl_sync(mask, base, leader);
        int pos = base + rank;
        g_tok[e][pos] = (t << 1) | slot;
        g_gw [e][pos] = w;
    }
}

// ---------------------------------------------------------------------------
// Kernel 4: grouped expert GEMM on warp tensor cores, fp16 single-term.
// grid = (TT/BM, 3, E). 128 threads = 4 m-warps x 1 n-warp (warp tile 32x80).
// B fragments loaded as jt-pairs via ldm_x4. 4-stage cp.async pipeline,
// one __syncthreads per chunk. Epilogue: plain stores into g_part.
// ---------------------------------------------------------------------------
#define HDR     1024
#define A_SZ    (BM * STRB)            // 6144 B per A stage
#define B_SZ    (BN * STRB)            // 3840 B per B stage
#define STG_SZ  (A_SZ + B_SZ)          // 9984 B per stage
#define OFF_A   0
#define OFF_B   A_SZ
#define SMEM_TOT (HDR + NSTAGE * STG_SZ)   // 40960 B -> 4 CTAs/SM

__global__ __launch_bounds__(128, 4)
void moe_mma_kernel(const float* __restrict__ eb) {
    const int e   = blockIdx.z;
    const int cnt = g_cnt[e];
    const int m0  = blockIdx.x * BM;
    if (m0 >= cnt) return;
    const int nb  = blockIdx.y * BN;      // 0, 80, 160

    extern __shared__ __align__(16) char smem[];
    int*   tsp = (int*)  smem;
    float* wsp = (float*)(smem + 512);
    const uint32_t sb = smem_u32(smem);

    const int tid  = threadIdx.x;
    const int lane = tid & 31;
    const int wid  = tid >> 5;           // m-warp 0..3
    const int m0w  = wid * 32;

    if (tid < BM) {
        int gr = m0 + tid;
        if (gr < cnt) { tsp[tid] = g_tok[e][gr]; wsp[tid] = g_gw[e][gr]; }
        else          { tsp[tid] = -1;           wsp[tid] = 0.f; }
    }
    __syncthreads();

    // --- cp.async issue for chunk c into stage stg ---
    auto issue = [&](int c, int stg) {
        uint32_t base = sb + HDR + stg * STG_SZ;
        // A: 128 rows x 2 segs of 16B = 256; 128 threads x 2 rounds
#pragma unroll
        for (int s = tid; s < BM * 2; s += 128) {
            int row = s >> 1, h = s & 1;
            int v = tsp[row];
            size_t so = (size_t)((v < 0) ? 0 : (v >> 1)) * DD + c * KCH + h * 8;
            int  sz = (v >= 0) ? 16 : 0;
            uint32_t d = (uint32_t)(row * STRB + h * 16);
            cp16(base + OFF_A + d, g_xf + so, sz);
        }
        // B: 80 rows x 2 segs = 160
#pragma unroll
        for (int s = tid; s < BN * 2; s += 128) {
            int row = s >> 1, h = s & 1;
            size_t so = ((size_t)e * DD + nb + row) * DD + c * KCH + h * 8;
            uint32_t d = (uint32_t)(row * STRB + h * 16);
            cp16(base + OFF_B + d, g_wf + so, 16);
        }
        CP_COMMIT();
    };

    // ldmatrix lane byte offsets (48B row stride), fixed across chunks
    const uint32_t a_off0 = (uint32_t)((m0w + (lane & 15)) * STRB + ((lane >> 4) << 4));
    // B pair-x4: lanes 0-7 -> rows r0..r0+7 khalf0, 8-15 -> khalf1,
    //            16-23 -> rows r0+8.., 24-31 -> khalf1
    const uint32_t b_off0 = (uint32_t)(((lane & 7) + ((lane >> 4) << 3)) * STRB
                                       + (((lane >> 3) & 1) << 4));

    float acc[2][10][4] = {};

    issue(0, 0);
    issue(1, 1);
    issue(2, 2);

    for (int c = 0; c < NCHUNK; c++) {
        const int stg = c % NSTAGE;
        if (c < NCHUNK - 2)       CP_WAIT(2);
        else if (c == NCHUNK - 2) CP_WAIT(1);
        else                      CP_WAIT(0);
        __syncthreads();        // stage c ready for all; all done with c-1

        if (c + 3 < NCHUNK) issue(c + 3, (c + 3) % NSTAGE);

        const uint32_t base = sb + HDR + stg * STG_SZ;
        const uint32_t a_base = base + OFF_A;
        const uint32_t b_base = base + OFF_B + b_off0;

        uint32_t ah[2][4];
#pragma unroll
        for (int mt = 0; mt < 2; mt++) {
            uint32_t ao = a_off0 + (uint32_t)(mt * 16 * STRB);
            ldm_x4(ah[mt], a_base + ao);
        }
#pragma unroll
        for (int jp = 0; jp < 5; jp++) {
            const int j0 = 2 * jp, j1 = 2 * jp + 1;
            uint32_t bh[4];
            ldm_x4(bh, b_base + (uint32_t)(jp * 16 * STRB));
            mma_fp16(acc[0][j0], ah[0], bh[0], bh[1]);
            mma_fp16(acc[1][j0], ah[1], bh[0], bh[1]);
            mma_fp16(acc[0][j1], ah[0], bh[2], bh[3]);
            mma_fp16(acc[1][j1], ah[1], bh[2], bh[3]);
        }
    }

    // --- epilogue: g_part[slot][t][n] = w_t * (acc + bias); plain stores ---
    const float* bp = eb + e * DD;
#pragma unroll
    for (int mt = 0; mt < 2; mt++) {
        int r1 = m0w + mt * 16 + (lane >> 2);
        int r2 = r1 + 8;
        int v1 = tsp[r1], v2 = tsp[r2];
        float w1 = wsp[r1], w2 = wsp[r2];
        float* o1 = (v1 < 0) ? nullptr : &g_part[v1 & 1][(size_t)(v1 >> 1) * DD];
        float* o2 = (v2 < 0) ? nullptr : &g_part[v2 & 1][(size_t)(v2 >> 1) * DD];
#pragma unroll
        for (int jt = 0; jt < 10; jt++) {
            int cc = nb + jt * 8 + 2 * (lane & 3);
            float b0v = bp[cc], b1v = bp[cc + 1];
            if (o1) {
                o1[cc]     = w1 * (acc[mt][jt][0] + b0v);
                o1[cc + 1] = w1 * (acc[mt][jt][1] + b1v);
            }
            if (o2) {
                o2[cc]     = w2 * (acc[mt][jt][2] + b0v);
                o2[cc + 1] = w2 * (acc[mt][jt][3] + b1v);
            }
        }
    }
}

// ---------------------------------------------------------------------------
// Kernel 5: combine — out = part[0] + part[1]
// ---------------------------------------------------------------------------
__global__ __launch_bounds__(256)
void combine_kernel(float4* __restrict__ out4, int n4) {
    int i = blockIdx.x * blockDim.x + threadIdx.x;
    if (i >= n4) return;
    float4 a = ((const float4*)g_part[0])[i];
    float4 b = ((const float4*)g_part[1])[i];
    out4[i] = make_float4(a.x + b.x, a.y + b.y, a.z + b.z, a.w + b.w);
}

// ---------------------------------------------------------------------------
extern "C" void kernel_launch(void* const* d_in, const int* in_sizes, int n_in,
                              void* d_out, int out_size) {
    const float* x  = (const float*)d_in[0];   // [B,S,D]
    const float* gw = (const float*)d_in[1];   // [E,D]
    const float* gb = (const float*)d_in[2];   // [E]
    const float* ew = (const float*)d_in[3];   // [E,D,D]
    const float* eb = (const float*)d_in[4];   // [E,D]
    float* out = (float*)d_out;                // [B,S,D] fp32

    unsigned short *wf;
    cudaGetSymbolAddress((void**)&wf, g_wf);

    int nw8 = EE * DD * DD / 8;                // 57600
    conv_kernel<<<(nw8 + 255) / 256, 256>>>(ew, wf, nw8);

    gate_kernel<<<(TT * 32) / 256, 256>>>(x, gw, gb);
    scatter_kernel<<<TT / 256, 256>>>();

    cudaFuncSetAttribute(moe_mma_kernel,
                         cudaFuncAttributeMaxDynamicSharedMemorySize, SMEM_TOT);
    dim3 ggrid(TT / BM, 3, EE);                // (256, 3, 8)
    moe_mma_kernel<<<ggrid, 128, SMEM_TOT>>>(eb);

    int n4 = out_size / 4;                     // 1,966,080
    combine_kernel<<<(n4 + 255) / 256, 256>>>((float4*)out, n4);
}